// round 11
// baseline (speedup 1.0000x reference)
#include <cuda_runtime.h>
#include <cuda_fp16.h>
#include <cstdint>

#define N_NODES_MAX 100000
#define N_EDGES_MAX 1600000

// ---------------- device scratch (no allocations allowed) ----------------
__device__ __half g_h[(size_t)N_NODES_MAX * 128];   // GEMM output (fp16, gathered)
__device__ __half g_y[(size_t)N_NODES_MAX * 128];   // agg output (fp16, GEMM A)
__device__ float g_dinv[N_NODES_MAX];
__device__ int   g_count[N_NODES_MAX];
__device__ int   g_fill[N_NODES_MAX];
__device__ int   g_rowptr[N_NODES_MAX + 1];
__device__ int   g_esrc[N_EDGES_MAX];
__device__ float g_enorm[N_EDGES_MAX];
__device__ int   g_bsums[256];
__device__ int   g_is32;
// transposed fp16 weights: WT[n][k]
__device__ __half g_wt1[128 * 384];
__device__ __half g_wt2[128 * 128];
__device__ __half g_wt3[128 * 128];
__device__ __half g_wt4[128 * 128];
__device__ __half g_wt5[64 * 128];

// ---------------- helpers ----------------
__device__ __forceinline__ int edge_val(const void* ei, int is32, long long idx) {
    if (is32) return ((const int*)ei)[idx];
    return (int)((const long long*)ei)[idx];
}
__device__ __forceinline__ void cp_async16(uint32_t dst, const void* src, int srcsize) {
    asm volatile("cp.async.ca.shared.global [%0], [%1], 16, %2;"
                 :: "r"(dst), "l"(src), "r"(srcsize));
}
__device__ __forceinline__ void cp_commit() { asm volatile("cp.async.commit_group;"); }
template<int N>
__device__ __forceinline__ void cp_wait() { asm volatile("cp.async.wait_group %0;" :: "n"(N)); }

__device__ __forceinline__ void ldsm_x4(uint32_t& r0, uint32_t& r1, uint32_t& r2, uint32_t& r3,
                                        uint32_t addr) {
    asm volatile("ldmatrix.sync.aligned.m8n8.x4.shared.b16 {%0,%1,%2,%3}, [%4];"
                 : "=r"(r0), "=r"(r1), "=r"(r2), "=r"(r3) : "r"(addr));
}

// ---------------- preprocessing kernels ----------------
__global__ void k_init(const void* ei, int E, long long N, int n) {
    int i = blockIdx.x * blockDim.x + threadIdx.x;
    if (i < n) { g_count[i] = 0; g_fill[i] = 0; }
    if (i == 0) {
        const long long* p = (const long long*)ei;
        int is32 = 0;
        for (int j = 0; j < 64 && j < E; j++) {
            long long v = p[j];
            if (v < 0 || v >= N) { is32 = 1; break; }
        }
        g_is32 = is32;
    }
}

__global__ void k_hist(const void* __restrict__ ei, int E) {
    int e = blockIdx.x * blockDim.x + threadIdx.x;
    if (e >= E) return;
    int is32 = g_is32;
    int d = edge_val(ei, is32, (long long)E + e);
    atomicAdd(&g_count[d], 1);
}

// scan over counts; also computes dinv (fused)
__global__ void k_scan1(int n) {
    __shared__ int s[1024];
    int t = threadIdx.x;
    int i = blockIdx.x * 1024 + t;
    int v = (i < n) ? g_count[i] : 0;
    if (i < n) g_dinv[i] = rsqrtf((float)v + 1.0f);
    s[t] = v;
    __syncthreads();
    #pragma unroll
    for (int off = 1; off < 1024; off <<= 1) {
        int x = (t >= off) ? s[t - off] : 0;
        __syncthreads();
        s[t] += x;
        __syncthreads();
    }
    if (i < n) g_rowptr[i] = s[t] - v;
    if (t == 1023) g_bsums[blockIdx.x] = s[1023];
}

// parallel block-sum scan (256 threads; nb <= 256)
__global__ void k_scan2(int nb, int n) {
    __shared__ int s[256];
    int t = threadIdx.x;
    int v = (t < nb) ? g_bsums[t] : 0;
    s[t] = v;
    __syncthreads();
    #pragma unroll
    for (int off = 1; off < 256; off <<= 1) {
        int x = (t >= off) ? s[t - off] : 0;
        __syncthreads();
        s[t] += x;
        __syncthreads();
    }
    if (t < nb) g_bsums[t] = s[t] - v;   // exclusive block offsets
    if (t == 255) g_rowptr[n] = s[255];
}

__global__ void k_scan3(int n) {
    int i = blockIdx.x * blockDim.x + threadIdx.x;
    if (i < n) g_rowptr[i] += g_bsums[i >> 10];
}

__global__ void k_scatter(const void* __restrict__ ei, int E) {
    int e = blockIdx.x * blockDim.x + threadIdx.x;
    if (e >= E) return;
    int is32 = g_is32;
    int s = edge_val(ei, is32, e);
    int d = edge_val(ei, is32, (long long)E + e);
    int pos = g_rowptr[d] + atomicAdd(&g_fill[d], 1);
    g_esrc[pos]  = s;
    g_enorm[pos] = g_dinv[s] * g_dinv[d];
}

// ---------------- all weight transposes (fp16) in one kernel ----------------
__global__ void k_wtrans_all(const float* __restrict__ W1, const float* __restrict__ W2,
                             const float* __restrict__ W3, const float* __restrict__ W4,
                             const float* __restrict__ W5) {
    int idx = blockIdx.x * 256 + threadIdx.x;
    if (idx < 49152) {                       // wt1: [128][384] from W1[384][128]
        int n = idx / 384, k = idx % 384;
        g_wt1[idx] = __float2half_rn(W1[(size_t)k * 128 + n]);
    } else if (idx < 49152 + 16384) {        // wt2
        int j = idx - 49152; int n = j / 128, k = j % 128;
        g_wt2[j] = __float2half_rn(W2[(size_t)k * 128 + n]);
    } else if (idx < 49152 + 32768) {        // wt3
        int j = idx - 49152 - 16384; int n = j / 128, k = j % 128;
        g_wt3[j] = __float2half_rn(W3[(size_t)k * 128 + n]);
    } else if (idx < 49152 + 49152) {        // wt4
        int j = idx - 49152 - 32768; int n = j / 128, k = j % 128;
        g_wt4[j] = __float2half_rn(W4[(size_t)k * 128 + n]);
    } else if (idx < 49152 + 49152 + 8192) { // wt5: [64][128] from W5[128][50]
        int j = idx - 49152 - 49152; int n = j / 128, k = j % 128;
        g_wt5[j] = (n < 50) ? __float2half_rn(W5[(size_t)k * 50 + n]) : __float2half_rn(0.f);
    }
}

// ---------------- GEMM1: fp32 A (fused cvt), 2-stage smem, double reg buffer --
// C[M, SC] = A32[M, KT] @ WT^T  (WT fp16 [BN][KT])
template<int KT, int BN, int SC>
__global__ __launch_bounds__(256, 2) void k_gemm_cvt(const float* __restrict__ A32,
                                                     const __half* __restrict__ WT,
                                                     __half* __restrict__ C, int M) {
    constexpr int BM = 128, BKH = 32;
    constexpr int WTN = BN / 4;
    constexpr int NTL = WTN / 8;
    constexpr int LDR = BKH + 8;            // 40 halves = 80B rows
    constexpr int NK  = KT / BKH;
    constexpr int AST = BM * LDR;
    constexpr int WST = BN * LDR;
    constexpr int WCH = BN * 4 / 256;

    extern __shared__ __half smem[];
    __half* Abase = smem;                    // 2 stages
    __half* Wbase = smem + 2 * AST;

    const int tid = threadIdx.x;
    const int wid = tid >> 5;
    const int lane = tid & 31;
    const int g = lane >> 2;
    const int t = lane & 3;
    const int warp_m = wid >> 2;
    const int warp_n = wid & 3;
    const int row0 = blockIdx.x * BM;

    const uint32_t sA = (uint32_t)__cvta_generic_to_shared(Abase);
    const uint32_t sW = (uint32_t)__cvta_generic_to_shared(Wbase);

    float acc[4][NTL][4];
    #pragma unroll
    for (int i = 0; i < 4; i++)
        #pragma unroll
        for (int j = 0; j < NTL; j++)
            #pragma unroll
            for (int r = 0; r < 4; r++) acc[i][j][r] = 0.f;

    float4 pa[2][4];

    auto cpW = [&](int i, int st) {
        const int kb = i * BKH;
        #pragma unroll
        for (int j = 0; j < WCH; j++) {
            int idx = tid + j * 256;
            int n = idx >> 2, ch = idx & 3;
            cp_async16(sW + (uint32_t)((st * WST + n * LDR + ch * 8) * 2),
                       WT + (size_t)n * KT + kb + ch * 8, 16);
        }
    };
    auto ldA = [&](int i, float4 (&p)[4]) {
        const int kb = i * BKH;
        #pragma unroll
        for (int j = 0; j < 4; j++) {
            int idx = tid + j * 256;
            int r = idx >> 3, c4 = idx & 7;
            int grow = row0 + r;
            p[j] = (grow < M)
                ? __ldg((const float4*)(A32 + (size_t)grow * KT + kb + c4 * 4))
                : make_float4(0.f, 0.f, 0.f, 0.f);
        }
    };
    auto stsA = [&](float4 (&p)[4], int st) {
        #pragma unroll
        for (int j = 0; j < 4; j++) {
            int idx = tid + j * 256;
            int r = idx >> 3, c4 = idx & 7;
            __half2 h0 = __floats2half2_rn(p[j].x, p[j].y);
            __half2 h1 = __floats2half2_rn(p[j].z, p[j].w);
            uint2 u;
            u.x = *(uint32_t*)&h0;
            u.y = *(uint32_t*)&h1;
            *(uint2*)(Abase + st * AST + r * LDR + c4 * 4) = u;
        }
    };
    auto compute = [&](int st) {
        #pragma unroll
        for (int ks = 0; ks < 2; ks++) {
            const int k16 = ks * 16;
            uint32_t bf[NTL][2];
            #pragma unroll
            for (int np = 0; np < NTL / 2; np++) {
                int n0 = warp_n * WTN + np * 16;
                uint32_t ad = sW + (uint32_t)(((st * WST) +
                              (n0 + (lane & 7) + ((lane >> 4) & 1) * 8) * LDR +
                              k16 + ((lane >> 3) & 1) * 8) * 2);
                ldsm_x4(bf[2 * np][0], bf[2 * np][1], bf[2 * np + 1][0], bf[2 * np + 1][1], ad);
            }
            #pragma unroll
            for (int mt = 0; mt < 4; mt++) {
                int mb = warp_m * 64 + mt * 16;
                uint32_t ad = sA + (uint32_t)(((st * AST) +
                              (mb + (lane & 15)) * LDR + k16 + (lane >> 4) * 8) * 2);
                uint32_t a0, a1, a2, a3;
                ldsm_x4(a0, a1, a2, a3, ad);
                #pragma unroll
                for (int nt = 0; nt < NTL; nt++) {
                    asm volatile(
                        "mma.sync.aligned.m16n8k16.row.col.f32.f16.f16.f32 "
                        "{%0,%1,%2,%3}, {%4,%5,%6,%7}, {%8,%9}, {%0,%1,%2,%3};"
                        : "+f"(acc[mt][nt][0]), "+f"(acc[mt][nt][1]),
                          "+f"(acc[mt][nt][2]), "+f"(acc[mt][nt][3])
                        : "r"(a0), "r"(a1), "r"(a2), "r"(a3),
                          "r"(bf[nt][0]), "r"(bf[nt][1]));
                }
            }
        }
    };

    // prologue: establish invariant — stage0 ready, pa[1]=A(1), LDG A(2)->pa[0] in flight
    ldA(0, pa[0]);
    cpW(0, 0); cp_commit();
    stsA(pa[0], 0);
    ldA(1, pa[1]);
    cpW(1, 1); cp_commit();
    ldA(2, pa[0]);
    cp_wait<1>();
    __syncthreads();

    for (int i = 0; i < NK; i++) {
        const int st = i & 1;
        compute(st);
        __syncthreads();                       // stage st consumed
        if (i + 1 < NK) stsA(pa[(i + 1) & 1], (i + 1) & 1);
        if (i + 3 < NK) ldA(i + 3, pa[(i + 1) & 1]);
        if (i + 2 < NK) cpW(i + 2, st);
        cp_commit();
        cp_wait<1>();
        __syncthreads();
    }

    // ---- epilogue: stage C in smem, coalesced STG.128 ----
    __syncthreads();
    constexpr int CLDR = BN + 8;
    __half* Cs = smem;
    #pragma unroll
    for (int mt = 0; mt < 4; mt++) {
        int rl = warp_m * 64 + mt * 16 + g;
        #pragma unroll
        for (int nt = 0; nt < NTL; nt++) {
            int col = warp_n * WTN + nt * 8 + t * 2;
            *(__half2*)(Cs + rl * CLDR + col) =
                __floats2half2_rn(acc[mt][nt][0], acc[mt][nt][1]);
            *(__half2*)(Cs + (rl + 8) * CLDR + col) =
                __floats2half2_rn(acc[mt][nt][2], acc[mt][nt][3]);
        }
    }
    __syncthreads();
    constexpr int CH8 = BN / 8;
    #pragma unroll
    for (int j = 0; j < (BM * CH8) / 256; j++) {
        int idx = tid + j * 256;
        int r = idx / CH8, c8 = idx % CH8;
        int grow = row0 + r;
        if (grow < M)
            *(uint4*)(C + (size_t)grow * SC + c8 * 8) = *(uint4*)(Cs + r * CLDR + c8 * 8);
    }
}

// ---------------- flat fp16 GEMM (K=128): one smem fill, zero in-loop syncs ---
// C[M, SC] = A[M, 128] @ WT^T  (WT fp16 [BN][128])
template<int BN, int SC>
__global__ __launch_bounds__(256, 2) void k_gemm_flat(const __half* __restrict__ A,
                                                      const __half* __restrict__ WT,
                                                      __half* __restrict__ C, int M) {
    constexpr int KT = 128, BM = 128;
    constexpr int WTN = BN / 4;
    constexpr int NTL = WTN / 8;
    constexpr int LDR = KT + 8;             // 136 halves = 272B rows, conflict-free
    constexpr int WCH = BN * 16 / 256;      // W 16B-chunks per thread (8 or 4)

    extern __shared__ __half smem[];
    __half* As = smem;                      // [BM][LDR]
    __half* Ws = smem + BM * LDR;           // [BN][LDR]

    const int tid = threadIdx.x;
    const int wid = tid >> 5;
    const int lane = tid & 31;
    const int g = lane >> 2;
    const int t = lane & 3;
    const int warp_m = wid >> 2;
    const int warp_n = wid & 3;
    const int row0 = blockIdx.x * BM;

    const uint32_t sA = (uint32_t)__cvta_generic_to_shared(As);
    const uint32_t sW = (uint32_t)__cvta_generic_to_shared(Ws);

    // ---- single cp.async burst: whole A tile + whole W ----
    #pragma unroll
    for (int j = 0; j < 8; j++) {                   // A: 128 rows x 16 chunks
        int idx = tid + j * 256;
        int r = idx >> 4, ch = idx & 15;
        int grow = row0 + r;
        cp_async16(sA + (uint32_t)((r * LDR + ch * 8) * 2),
                   A + (size_t)grow * KT + ch * 8, grow < M ? 16 : 0);
    }
    #pragma unroll
    for (int j = 0; j < WCH; j++) {                 // W: BN rows x 16 chunks
        int idx = tid + j * 256;
        int r = idx >> 4, ch = idx & 15;
        cp_async16(sW + (uint32_t)((r * LDR + ch * 8) * 2),
                   WT + (size_t)r * KT + ch * 8, 16);
    }
    cp_commit();

    float acc[4][NTL][4];
    #pragma unroll
    for (int i = 0; i < 4; i++)
        #pragma unroll
        for (int j = 0; j < NTL; j++)
            #pragma unroll
            for (int r = 0; r < 4; r++) acc[i][j][r] = 0.f;

    cp_wait<0>();
    __syncthreads();

    // ---- 8 uninterrupted k16 steps ----
    #pragma unroll
    for (int ks = 0; ks < 8; ks++) {
        const int k16 = ks * 16;
        uint32_t bf[NTL][2];
        #pragma unroll
        for (int np = 0; np < NTL / 2; np++) {
            int n0 = warp_n * WTN + np * 16;
            uint32_t ad = sW + (uint32_t)(((n0 + (lane & 7) + ((lane >> 4) & 1) * 8) * LDR +
                          k16 + ((lane >> 3) & 1) * 8) * 2);
            ldsm_x4(bf[2 * np][0], bf[2 * np][1], bf[2 * np + 1][0], bf[2 * np + 1][1], ad);
        }
        #pragma unroll
        for (int mt = 0; mt < 4; mt++) {
            int mb = warp_m * 64 + mt * 16;
            uint32_t ad = sA + (uint32_t)(((mb + (lane & 15)) * LDR + k16 + (lane >> 4) * 8) * 2);
            uint32_t a0, a1, a2, a3;
            ldsm_x4(a0, a1, a2, a3, ad);
            #pragma unroll
            for (int nt = 0; nt < NTL; nt++) {
                asm volatile(
                    "mma.sync.aligned.m16n8k16.row.col.f32.f16.f16.f32 "
                    "{%0,%1,%2,%3}, {%4,%5,%6,%7}, {%8,%9}, {%0,%1,%2,%3};"
                    : "+f"(acc[mt][nt][0]), "+f"(acc[mt][nt][1]),
                      "+f"(acc[mt][nt][2]), "+f"(acc[mt][nt][3])
                    : "r"(a0), "r"(a1), "r"(a2), "r"(a3),
                      "r"(bf[nt][0]), "r"(bf[nt][1]));
            }
        }
    }

    // ---- epilogue: stage C in smem, coalesced STG.128 ----
    __syncthreads();
    constexpr int CLDR = BN + 8;
    __half* Cs = smem;
    #pragma unroll
    for (int mt = 0; mt < 4; mt++) {
        int rl = warp_m * 64 + mt * 16 + g;
        #pragma unroll
        for (int nt = 0; nt < NTL; nt++) {
            int col = warp_n * WTN + nt * 8 + t * 2;
            *(__half2*)(Cs + rl * CLDR + col) =
                __floats2half2_rn(acc[mt][nt][0], acc[mt][nt][1]);
            *(__half2*)(Cs + (rl + 8) * CLDR + col) =
                __floats2half2_rn(acc[mt][nt][2], acc[mt][nt][3]);
        }
    }
    __syncthreads();
    constexpr int CH8 = BN / 8;
    #pragma unroll
    for (int j = 0; j < (BM * CH8) / 256; j++) {
        int idx = tid + j * 256;
        int r = idx / CH8, c8 = idx % CH8;
        int grow = row0 + r;
        if (grow < M)
            *(uint4*)(C + (size_t)grow * SC + c8 * 8) = *(uint4*)(Cs + r * CLDR + c8 * 8);
    }
}

// ---------------- aggregation (C=128): warp per node, half in/half out -------
__global__ __launch_bounds__(256) void k_agg128(const __half* __restrict__ hin,
                                                const float* __restrict__ b,
                                                __half* __restrict__ out, int n) {
    int warp = (blockIdx.x * blockDim.x + threadIdx.x) >> 5;
    int lane = threadIdx.x & 31;
    if (warp >= n) return;
    const uint2* __restrict__ h2 = (const uint2*)hin;   // 4 halves per uint2; 32/row
    int e = g_rowptr[warp];
    const int e1 = g_rowptr[warp + 1];

    float4 acc = make_float4(0.f, 0.f, 0.f, 0.f);

    for (; e + 8 <= e1; e += 8) {
        int   s[8]; float w[8]; uint2 v[8];
        #pragma unroll
        for (int j = 0; j < 8; j++) { s[j] = g_esrc[e + j]; w[j] = g_enorm[e + j]; }
        #pragma unroll
        for (int j = 0; j < 8; j++) v[j] = __ldg(h2 + s[j] * 32 + lane);
        #pragma unroll
        for (int j = 0; j < 8; j++) {
            float2 f0 = __half22float2(*(__half2*)&v[j].x);
            float2 f1 = __half22float2(*(__half2*)&v[j].y);
            acc.x += w[j] * f0.x; acc.y += w[j] * f0.y;
            acc.z += w[j] * f1.x; acc.w += w[j] * f1.y;
        }
    }
    for (; e < e1; e++) {
        int s0 = g_esrc[e];
        float n0 = g_enorm[e];
        uint2 v0 = __ldg(h2 + s0 * 32 + lane);
        float2 f0 = __half22float2(*(__half2*)&v0.x);
        float2 f1 = __half22float2(*(__half2*)&v0.y);
        acc.x += n0 * f0.x; acc.y += n0 * f0.y;
        acc.z += n0 * f1.x; acc.w += n0 * f1.y;
    }

    float di = g_dinv[warp];
    float sl = di * di;
    uint2 vr = __ldg(h2 + warp * 32 + lane);
    float2 vi0 = __half22float2(*(__half2*)&vr.x);
    float2 vi1 = __half22float2(*(__half2*)&vr.y);
    float4 vb = __ldg((const float4*)b + lane);
    __half2 o0 = __floats2half2_rn(fmaxf(acc.x + sl * vi0.x + vb.x, 0.f),
                                   fmaxf(acc.y + sl * vi0.y + vb.y, 0.f));
    __half2 o1 = __floats2half2_rn(fmaxf(acc.z + sl * vi1.x + vb.z, 0.f),
                                   fmaxf(acc.w + sl * vi1.y + vb.w, 0.f));
    uint2 o;
    o.x = *(uint32_t*)&o0;
    o.y = *(uint32_t*)&o1;
    ((uint2*)out)[warp * 32 + lane] = o;
}

// ---------------- final aggregation (C=50, half input, no relu) --------------
__global__ __launch_bounds__(256) void k_agg_fin(const __half* __restrict__ h,
                                                 const float* __restrict__ b,
                                                 float* __restrict__ out, int n) {
    int warp = (blockIdx.x * blockDim.x + threadIdx.x) >> 5;
    int lane = threadIdx.x & 31;
    if (warp >= n) return;
    const int i = warp;
    int e = g_rowptr[i];
    const int e1 = g_rowptr[i + 1];
    const int f0 = lane;            // < 32
    const int f1 = lane + 32;       // < 50 for lanes 0..17

    float a0 = 0.f, a1 = 0.f;
    for (; e + 4 <= e1; e += 4) {
        int s0 = g_esrc[e], s1 = g_esrc[e + 1], s2 = g_esrc[e + 2], s3 = g_esrc[e + 3];
        float n0 = g_enorm[e], n1 = g_enorm[e + 1], n2 = g_enorm[e + 2], n3 = g_enorm[e + 3];
        const __half* p0 = h + (size_t)s0 * 64;
        const __half* p1 = h + (size_t)s1 * 64;
        const __half* p2 = h + (size_t)s2 * 64;
        const __half* p3 = h + (size_t)s3 * 64;
        a0 += n0 * __half2float(__ldg(p0 + f0));
        a0 += n1 * __half2float(__ldg(p1 + f0));
        a0 += n2 * __half2float(__ldg(p2 + f0));
        a0 += n3 * __half2float(__ldg(p3 + f0));
        if (f1 < 50) {
            a1 += n0 * __half2float(__ldg(p0 + f1));
            a1 += n1 * __half2float(__ldg(p1 + f1));
            a1 += n2 * __half2float(__ldg(p2 + f1));
            a1 += n3 * __half2float(__ldg(p3 + f1));
        }
    }
    for (; e < e1; e++) {
        int s0 = g_esrc[e];
        float n0 = g_enorm[e];
        const __half* p0 = h + (size_t)s0 * 64;
        a0 += n0 * __half2float(__ldg(p0 + f0));
        if (f1 < 50) a1 += n0 * __half2float(__ldg(p0 + f1));
    }

    float di = g_dinv[i];
    float sl = di * di;
    const __half* hi = h + (size_t)i * 64;
    out[(size_t)i * 50 + f0] = a0 + sl * __half2float(__ldg(hi + f0)) + __ldg(b + f0);
    if (f1 < 50)
        out[(size_t)i * 50 + f1] = a1 + sl * __half2float(__ldg(hi + f1)) + __ldg(b + f1);
}

// ---------------- launch ----------------
extern "C" void kernel_launch(void* const* d_in, const int* in_sizes, int n_in,
                              void* d_out, int out_size) {
    const float* x  = (const float*)d_in[0];
    const void*  ei = d_in[1];
    const float* W1 = (const float*)d_in[2];  const float* b1 = (const float*)d_in[3];
    const float* W2 = (const float*)d_in[4];  const float* b2 = (const float*)d_in[5];
    const float* W3 = (const float*)d_in[6];  const float* b3 = (const float*)d_in[7];
    const float* W4 = (const float*)d_in[8];  const float* b4 = (const float*)d_in[9];
    const float* W5 = (const float*)d_in[10]; const float* b5 = (const float*)d_in[11];

    const int N = in_sizes[0] / 384;
    const int E = in_sizes[1] / 2;

    __half *h, *y, *wt1, *wt2, *wt3, *wt4, *wt5;
    cudaGetSymbolAddress((void**)&h, g_h);
    cudaGetSymbolAddress((void**)&y, g_y);
    cudaGetSymbolAddress((void**)&wt1, g_wt1);
    cudaGetSymbolAddress((void**)&wt2, g_wt2);
    cudaGetSymbolAddress((void**)&wt3, g_wt3);
    cudaGetSymbolAddress((void**)&wt4, g_wt4);
    cudaGetSymbolAddress((void**)&wt5, g_wt5);

    const int T = 256;
    const int gN = (N + T - 1) / T;
    const int gE = (E + T - 1) / T;
    const int nb = (N + 1023) / 1024;
    const int gm = (N + 127) / 128;
    const int ga = (N + 7) / 8;

    const int smemCVT  = 2 * (128 + 128) * 40 * 2;  // 40960
    const int smemF128 = (128 + 128) * 136 * 2;     // 69632
    const int smemF64  = (128 + 64) * 136 * 2;      // 52224
    cudaFuncSetAttribute(k_gemm_cvt<384, 128, 128>,
                         cudaFuncAttributeMaxDynamicSharedMemorySize, smemCVT);
    cudaFuncSetAttribute(k_gemm_flat<128, 128>,
                         cudaFuncAttributeMaxDynamicSharedMemorySize, smemF128);
    cudaFuncSetAttribute(k_gemm_flat<64, 64>,
                         cudaFuncAttributeMaxDynamicSharedMemorySize, smemF64);

    // launch order keeps GEMM1 at launch index 3 (ncu capture slot)
    k_init<<<gN, T>>>(ei, E, (long long)N, N);
    k_wtrans_all<<<(106496 + 255) / 256, T>>>(W1, W2, W3, W4, W5);
    k_hist<<<gE, T>>>(ei, E);
    k_gemm_cvt<384, 128, 128><<<gm, T, smemCVT>>>(x, wt1, h, N);   // GEMM1 (+cvt)
    k_scan1<<<nb, 1024>>>(N);
    k_scan2<<<1, 256>>>(nb, N);
    k_scan3<<<gN, T>>>(N);
    k_scatter<<<gE, T>>>(ei, E);

    // layer 1 aggregation (half gathers -> fp16 y)
    k_agg128<<<ga, T>>>(h, b1, y, N);
    // layers 2-4 (flat GEMMs)
    k_gemm_flat<128, 128><<<gm, T, smemF128>>>(y, wt2, h, N);
    k_agg128<<<ga, T>>>(h, b2, y, N);
    k_gemm_flat<128, 128><<<gm, T, smemF128>>>(y, wt3, h, N);
    k_agg128<<<ga, T>>>(h, b3, y, N);
    k_gemm_flat<128, 128><<<gm, T, smemF128>>>(y, wt4, h, N);
    k_agg128<<<ga, T>>>(h, b4, y, N);
    // layer 5: 128 -> 50 (64 padded cols), then final aggregation
    k_gemm_flat<64, 64><<<gm, T, smemF64>>>(y, wt5, h, N);
    k_agg_fin<<<ga, T>>>(h, b5, (float*)d_out, N);
}

// round 12
// speedup vs baseline: 1.0761x; 1.0761x over previous
#include <cuda_runtime.h>
#include <cuda_fp16.h>
#include <cstdint>

#define N_NODES_MAX 100000
#define N_EDGES_MAX 1600000

// ---------------- device scratch (no allocations allowed) ----------------
__device__ __half g_h[(size_t)N_NODES_MAX * 128];   // GEMM output (fp16, gathered)
__device__ __half g_y[(size_t)N_NODES_MAX * 128];   // agg output (fp16, GEMM A)
__device__ float g_dinv[N_NODES_MAX];
__device__ int   g_count[N_NODES_MAX];
__device__ int   g_fill[N_NODES_MAX];
__device__ int   g_rowptr[N_NODES_MAX + 1];
__device__ int   g_esrc[N_EDGES_MAX];
__device__ float g_enorm[N_EDGES_MAX];
__device__ int   g_bsums[256];
__device__ int   g_is32;
// transposed fp16 weights: WT[n][k]
__device__ __half g_wt1[128 * 384];
__device__ __half g_wt2[128 * 128];
__device__ __half g_wt3[128 * 128];
__device__ __half g_wt4[128 * 128];
__device__ __half g_wt5[64 * 128];

// ---------------- helpers ----------------
__device__ __forceinline__ int edge_val(const void* ei, int is32, long long idx) {
    if (is32) return ((const int*)ei)[idx];
    return (int)((const long long*)ei)[idx];
}
__device__ __forceinline__ void cp_async16(uint32_t dst, const void* src, int srcsize) {
    asm volatile("cp.async.ca.shared.global [%0], [%1], 16, %2;"
                 :: "r"(dst), "l"(src), "r"(srcsize));
}
__device__ __forceinline__ void cp_commit() { asm volatile("cp.async.commit_group;"); }
template<int N>
__device__ __forceinline__ void cp_wait() { asm volatile("cp.async.wait_group %0;" :: "n"(N)); }

__device__ __forceinline__ void ldsm_x4(uint32_t& r0, uint32_t& r1, uint32_t& r2, uint32_t& r3,
                                        uint32_t addr) {
    asm volatile("ldmatrix.sync.aligned.m8n8.x4.shared.b16 {%0,%1,%2,%3}, [%4];"
                 : "=r"(r0), "=r"(r1), "=r"(r2), "=r"(r3) : "r"(addr));
}

// ---------------- preprocessing kernels ----------------
__global__ void k_init(const void* ei, int E, long long N, int n) {
    int i = blockIdx.x * blockDim.x + threadIdx.x;
    if (i < n) { g_count[i] = 0; g_fill[i] = 0; }
    if (i == 0) {
        const long long* p = (const long long*)ei;
        int is32 = 0;
        for (int j = 0; j < 64 && j < E; j++) {
            long long v = p[j];
            if (v < 0 || v >= N) { is32 = 1; break; }
        }
        g_is32 = is32;
    }
}

__global__ void k_hist(const void* __restrict__ ei, int E) {
    int e = blockIdx.x * blockDim.x + threadIdx.x;
    if (e >= E) return;
    int is32 = g_is32;
    int d = edge_val(ei, is32, (long long)E + e);
    atomicAdd(&g_count[d], 1);
}

// scan over counts; also computes dinv (fused)
__global__ void k_scan1(int n) {
    __shared__ int s[1024];
    int t = threadIdx.x;
    int i = blockIdx.x * 1024 + t;
    int v = (i < n) ? g_count[i] : 0;
    if (i < n) g_dinv[i] = rsqrtf((float)v + 1.0f);
    s[t] = v;
    __syncthreads();
    #pragma unroll
    for (int off = 1; off < 1024; off <<= 1) {
        int x = (t >= off) ? s[t - off] : 0;
        __syncthreads();
        s[t] += x;
        __syncthreads();
    }
    if (i < n) g_rowptr[i] = s[t] - v;
    if (t == 1023) g_bsums[blockIdx.x] = s[1023];
}

// parallel block-sum scan (256 threads; nb <= 256)
__global__ void k_scan2(int nb, int n) {
    __shared__ int s[256];
    int t = threadIdx.x;
    int v = (t < nb) ? g_bsums[t] : 0;
    s[t] = v;
    __syncthreads();
    #pragma unroll
    for (int off = 1; off < 256; off <<= 1) {
        int x = (t >= off) ? s[t - off] : 0;
        __syncthreads();
        s[t] += x;
        __syncthreads();
    }
    if (t < nb) g_bsums[t] = s[t] - v;   // exclusive block offsets
    if (t == 255) g_rowptr[n] = s[255];
}

__global__ void k_scan3(int n) {
    int i = blockIdx.x * blockDim.x + threadIdx.x;
    if (i < n) g_rowptr[i] += g_bsums[i >> 10];
}

__global__ void k_scatter(const void* __restrict__ ei, int E) {
    int e = blockIdx.x * blockDim.x + threadIdx.x;
    if (e >= E) return;
    int is32 = g_is32;
    int s = edge_val(ei, is32, e);
    int d = edge_val(ei, is32, (long long)E + e);
    int pos = g_rowptr[d] + atomicAdd(&g_fill[d], 1);
    g_esrc[pos]  = s;
    g_enorm[pos] = g_dinv[s] * g_dinv[d];
}

// ---------------- all weight transposes (fp16) in one kernel ----------------
__global__ void k_wtrans_all(const float* __restrict__ W1, const float* __restrict__ W2,
                             const float* __restrict__ W3, const float* __restrict__ W4,
                             const float* __restrict__ W5) {
    int idx = blockIdx.x * 256 + threadIdx.x;
    if (idx < 49152) {                       // wt1: [128][384] from W1[384][128]
        int n = idx / 384, k = idx % 384;
        g_wt1[idx] = __float2half_rn(W1[(size_t)k * 128 + n]);
    } else if (idx < 49152 + 16384) {        // wt2
        int j = idx - 49152; int n = j / 128, k = j % 128;
        g_wt2[j] = __float2half_rn(W2[(size_t)k * 128 + n]);
    } else if (idx < 49152 + 32768) {        // wt3
        int j = idx - 49152 - 16384; int n = j / 128, k = j % 128;
        g_wt3[j] = __float2half_rn(W3[(size_t)k * 128 + n]);
    } else if (idx < 49152 + 49152) {        // wt4
        int j = idx - 49152 - 32768; int n = j / 128, k = j % 128;
        g_wt4[j] = __float2half_rn(W4[(size_t)k * 128 + n]);
    } else if (idx < 49152 + 49152 + 8192) { // wt5: [64][128] from W5[128][50]
        int j = idx - 49152 - 49152; int n = j / 128, k = j % 128;
        g_wt5[j] = (n < 50) ? __float2half_rn(W5[(size_t)k * 50 + n]) : __float2half_rn(0.f);
    }
}

// ---------------- GEMM1: fp32 A (fused cvt), 2-stage smem, single reg buffer --
// (R9 structure, measured 49.1us: LDG(i+2) issued right after STS(i+1).)
template<int KT, int BN, int SC>
__global__ __launch_bounds__(256, 2) void k_gemm_cvt(const float* __restrict__ A32,
                                                     const __half* __restrict__ WT,
                                                     __half* __restrict__ C, int M) {
    constexpr int BM = 128, BKH = 32;
    constexpr int WTN = BN / 4;
    constexpr int NTL = WTN / 8;
    constexpr int LDR = BKH + 8;            // 40 halves = 80B rows
    constexpr int NK  = KT / BKH;
    constexpr int AST = BM * LDR;
    constexpr int WST = BN * LDR;
    constexpr int WCH = BN * 4 / 256;

    extern __shared__ __half smem[];
    __half* Abase = smem;                    // 2 stages
    __half* Wbase = smem + 2 * AST;

    const int tid = threadIdx.x;
    const int wid = tid >> 5;
    const int lane = tid & 31;
    const int g = lane >> 2;
    const int t = lane & 3;
    const int warp_m = wid >> 2;
    const int warp_n = wid & 3;
    const int row0 = blockIdx.x * BM;

    const uint32_t sA = (uint32_t)__cvta_generic_to_shared(Abase);
    const uint32_t sW = (uint32_t)__cvta_generic_to_shared(Wbase);

    float acc[4][NTL][4];
    #pragma unroll
    for (int i = 0; i < 4; i++)
        #pragma unroll
        for (int j = 0; j < NTL; j++)
            #pragma unroll
            for (int r = 0; r < 4; r++) acc[i][j][r] = 0.f;

    float4 pa[4];

    auto cpW = [&](int i, int st) {
        const int kb = i * BKH;
        #pragma unroll
        for (int j = 0; j < WCH; j++) {
            int idx = tid + j * 256;
            int n = idx >> 2, ch = idx & 3;
            cp_async16(sW + (uint32_t)((st * WST + n * LDR + ch * 8) * 2),
                       WT + (size_t)n * KT + kb + ch * 8, 16);
        }
    };
    auto ldA = [&](int i) {
        const int kb = i * BKH;
        #pragma unroll
        for (int j = 0; j < 4; j++) {
            int idx = tid + j * 256;
            int r = idx >> 3, c4 = idx & 7;
            int grow = row0 + r;
            pa[j] = (grow < M)
                ? __ldg((const float4*)(A32 + (size_t)grow * KT + kb + c4 * 4))
                : make_float4(0.f, 0.f, 0.f, 0.f);
        }
    };
    auto stsA = [&](int st) {
        #pragma unroll
        for (int j = 0; j < 4; j++) {
            int idx = tid + j * 256;
            int r = idx >> 3, c4 = idx & 7;
            __half2 h0 = __floats2half2_rn(pa[j].x, pa[j].y);
            __half2 h1 = __floats2half2_rn(pa[j].z, pa[j].w);
            uint2 u;
            u.x = *(uint32_t*)&h0;
            u.y = *(uint32_t*)&h1;
            *(uint2*)(Abase + st * AST + r * LDR + c4 * 4) = u;
        }
    };
    auto compute = [&](int st) {
        #pragma unroll
        for (int ks = 0; ks < 2; ks++) {
            const int k16 = ks * 16;
            uint32_t bf[NTL][2];
            #pragma unroll
            for (int np = 0; np < NTL / 2; np++) {
                int n0 = warp_n * WTN + np * 16;
                uint32_t ad = sW + (uint32_t)(((st * WST) +
                              (n0 + (lane & 7) + ((lane >> 4) & 1) * 8) * LDR +
                              k16 + ((lane >> 3) & 1) * 8) * 2);
                ldsm_x4(bf[2 * np][0], bf[2 * np][1], bf[2 * np + 1][0], bf[2 * np + 1][1], ad);
            }
            #pragma unroll
            for (int mt = 0; mt < 4; mt++) {
                int mb = warp_m * 64 + mt * 16;
                uint32_t ad = sA + (uint32_t)(((st * AST) +
                              (mb + (lane & 15)) * LDR + k16 + (lane >> 4) * 8) * 2);
                uint32_t a0, a1, a2, a3;
                ldsm_x4(a0, a1, a2, a3, ad);
                #pragma unroll
                for (int nt = 0; nt < NTL; nt++) {
                    asm volatile(
                        "mma.sync.aligned.m16n8k16.row.col.f32.f16.f16.f32 "
                        "{%0,%1,%2,%3}, {%4,%5,%6,%7}, {%8,%9}, {%0,%1,%2,%3};"
                        : "+f"(acc[mt][nt][0]), "+f"(acc[mt][nt][1]),
                          "+f"(acc[mt][nt][2]), "+f"(acc[mt][nt][3])
                        : "r"(a0), "r"(a1), "r"(a2), "r"(a3),
                          "r"(bf[nt][0]), "r"(bf[nt][1]));
                }
            }
        }
    };

    ldA(0);
    cpW(0, 0); cp_commit();
    stsA(0);
    ldA(1);
    cpW(1, 1); cp_commit();
    cp_wait<1>();
    __syncthreads();

    for (int i = 0; i < NK; i++) {
        const int st = i & 1;
        compute(st);
        __syncthreads();                       // stage st fully consumed
        if (i + 1 < NK) stsA((i + 1) & 1);     // A(i+1) regs -> other stage
        if (i + 2 < NK) { ldA(i + 2); cpW(i + 2, st); }
        cp_commit();
        cp_wait<1>();
        __syncthreads();
    }

    // ---- epilogue: stage C in smem, coalesced STG.128 ----
    __syncthreads();
    constexpr int CLDR = BN + 8;
    __half* Cs = smem;
    #pragma unroll
    for (int mt = 0; mt < 4; mt++) {
        int rl = warp_m * 64 + mt * 16 + g;
        #pragma unroll
        for (int nt = 0; nt < NTL; nt++) {
            int col = warp_n * WTN + nt * 8 + t * 2;
            *(__half2*)(Cs + rl * CLDR + col) =
                __floats2half2_rn(acc[mt][nt][0], acc[mt][nt][1]);
            *(__half2*)(Cs + (rl + 8) * CLDR + col) =
                __floats2half2_rn(acc[mt][nt][2], acc[mt][nt][3]);
        }
    }
    __syncthreads();
    constexpr int CH8 = BN / 8;
    #pragma unroll
    for (int j = 0; j < (BM * CH8) / 256; j++) {
        int idx = tid + j * 256;
        int r = idx / CH8, c8 = idx % CH8;
        int grow = row0 + r;
        if (grow < M)
            *(uint4*)(C + (size_t)grow * SC + c8 * 8) = *(uint4*)(Cs + r * CLDR + c8 * 8);
    }
}

// ---------------- flat fp16 GEMM (K=128): one smem fill, zero in-loop syncs ---
template<int BN, int SC>
__global__ __launch_bounds__(256, 2) void k_gemm_flat(const __half* __restrict__ A,
                                                      const __half* __restrict__ WT,
                                                      __half* __restrict__ C, int M) {
    constexpr int KT = 128, BM = 128;
    constexpr int WTN = BN / 4;
    constexpr int NTL = WTN / 8;
    constexpr int LDR = KT + 8;             // 136 halves = 272B rows, conflict-free
    constexpr int WCH = BN * 16 / 256;      // W 16B-chunks per thread (8 or 4)

    extern __shared__ __half smem[];
    __half* As = smem;                      // [BM][LDR]
    __half* Ws = smem + BM * LDR;           // [BN][LDR]

    const int tid = threadIdx.x;
    const int wid = tid >> 5;
    const int lane = tid & 31;
    const int g = lane >> 2;
    const int t = lane & 3;
    const int warp_m = wid >> 2;
    const int warp_n = wid & 3;
    const int row0 = blockIdx.x * BM;

    const uint32_t sA = (uint32_t)__cvta_generic_to_shared(As);
    const uint32_t sW = (uint32_t)__cvta_generic_to_shared(Ws);

    // ---- single cp.async burst: whole A tile + whole W ----
    #pragma unroll
    for (int j = 0; j < 8; j++) {                   // A: 128 rows x 16 chunks
        int idx = tid + j * 256;
        int r = idx >> 4, ch = idx & 15;
        int grow = row0 + r;
        cp_async16(sA + (uint32_t)((r * LDR + ch * 8) * 2),
                   A + (size_t)grow * KT + ch * 8, grow < M ? 16 : 0);
    }
    #pragma unroll
    for (int j = 0; j < WCH; j++) {                 // W: BN rows x 16 chunks
        int idx = tid + j * 256;
        int r = idx >> 4, ch = idx & 15;
        cp_async16(sW + (uint32_t)((r * LDR + ch * 8) * 2),
                   WT + (size_t)r * KT + ch * 8, 16);
    }
    cp_commit();

    float acc[4][NTL][4];
    #pragma unroll
    for (int i = 0; i < 4; i++)
        #pragma unroll
        for (int j = 0; j < NTL; j++)
            #pragma unroll
            for (int r = 0; r < 4; r++) acc[i][j][r] = 0.f;

    cp_wait<0>();
    __syncthreads();

    // ---- 8 uninterrupted k16 steps ----
    #pragma unroll
    for (int ks = 0; ks < 8; ks++) {
        const int k16 = ks * 16;
        uint32_t bf[NTL][2];
        #pragma unroll
        for (int np = 0; np < NTL / 2; np++) {
            int n0 = warp_n * WTN + np * 16;
            uint32_t ad = sW + (uint32_t)(((n0 + (lane & 7) + ((lane >> 4) & 1) * 8) * LDR +
                          k16 + ((lane >> 3) & 1) * 8) * 2);
            ldsm_x4(bf[2 * np][0], bf[2 * np][1], bf[2 * np + 1][0], bf[2 * np + 1][1], ad);
        }
        #pragma unroll
        for (int mt = 0; mt < 4; mt++) {
            int mb = warp_m * 64 + mt * 16;
            uint32_t ad = sA + (uint32_t)(((mb + (lane & 15)) * LDR + k16 + (lane >> 4) * 8) * 2);
            uint32_t a0, a1, a2, a3;
            ldsm_x4(a0, a1, a2, a3, ad);
            #pragma unroll
            for (int nt = 0; nt < NTL; nt++) {
                asm volatile(
                    "mma.sync.aligned.m16n8k16.row.col.f32.f16.f16.f32 "
                    "{%0,%1,%2,%3}, {%4,%5,%6,%7}, {%8,%9}, {%0,%1,%2,%3};"
                    : "+f"(acc[mt][nt][0]), "+f"(acc[mt][nt][1]),
                      "+f"(acc[mt][nt][2]), "+f"(acc[mt][nt][3])
                    : "r"(a0), "r"(a1), "r"(a2), "r"(a3),
                      "r"(bf[nt][0]), "r"(bf[nt][1]));
            }
        }
    }

    // ---- epilogue: stage C in smem, coalesced STG.128 ----
    __syncthreads();
    constexpr int CLDR = BN + 8;
    __half* Cs = smem;
    #pragma unroll
    for (int mt = 0; mt < 4; mt++) {
        int rl = warp_m * 64 + mt * 16 + g;
        #pragma unroll
        for (int nt = 0; nt < NTL; nt++) {
            int col = warp_n * WTN + nt * 8 + t * 2;
            *(__half2*)(Cs + rl * CLDR + col) =
                __floats2half2_rn(acc[mt][nt][0], acc[mt][nt][1]);
            *(__half2*)(Cs + (rl + 8) * CLDR + col) =
                __floats2half2_rn(acc[mt][nt][2], acc[mt][nt][3]);
        }
    }
    __syncthreads();
    constexpr int CH8 = BN / 8;
    #pragma unroll
    for (int j = 0; j < (BM * CH8) / 256; j++) {
        int idx = tid + j * 256;
        int r = idx / CH8, c8 = idx % CH8;
        int grow = row0 + r;
        if (grow < M)
            *(uint4*)(C + (size_t)grow * SC + c8 * 8) = *(uint4*)(Cs + r * CLDR + c8 * 8);
    }
}

// ---------------- aggregation (C=128): warp per node, half in/half out -------
__global__ __launch_bounds__(256) void k_agg128(const __half* __restrict__ hin,
                                                const float* __restrict__ b,
                                                __half* __restrict__ out, int n) {
    int warp = (blockIdx.x * blockDim.x + threadIdx.x) >> 5;
    int lane = threadIdx.x & 31;
    if (warp >= n) return;
    const uint2* __restrict__ h2 = (const uint2*)hin;   // 4 halves per uint2; 32/row
    int e = g_rowptr[warp];
    const int e1 = g_rowptr[warp + 1];

    float4 acc = make_float4(0.f, 0.f, 0.f, 0.f);

    for (; e + 8 <= e1; e += 8) {
        int   s[8]; float w[8]; uint2 v[8];
        #pragma unroll
        for (int j = 0; j < 8; j++) { s[j] = g_esrc[e + j]; w[j] = g_enorm[e + j]; }
        #pragma unroll
        for (int j = 0; j < 8; j++) v[j] = __ldg(h2 + s[j] * 32 + lane);
        #pragma unroll
        for (int j = 0; j < 8; j++) {
            float2 f0 = __half22float2(*(__half2*)&v[j].x);
            float2 f1 = __half22float2(*(__half2*)&v[j].y);
            acc.x += w[j] * f0.x; acc.y += w[j] * f0.y;
            acc.z += w[j] * f1.x; acc.w += w[j] * f1.y;
        }
    }
    for (; e < e1; e++) {
        int s0 = g_esrc[e];
        float n0 = g_enorm[e];
        uint2 v0 = __ldg(h2 + s0 * 32 + lane);
        float2 f0 = __half22float2(*(__half2*)&v0.x);
        float2 f1 = __half22float2(*(__half2*)&v0.y);
        acc.x += n0 * f0.x; acc.y += n0 * f0.y;
        acc.z += n0 * f1.x; acc.w += n0 * f1.y;
    }

    float di = g_dinv[warp];
    float sl = di * di;
    uint2 vr = __ldg(h2 + warp * 32 + lane);
    float2 vi0 = __half22float2(*(__half2*)&vr.x);
    float2 vi1 = __half22float2(*(__half2*)&vr.y);
    float4 vb = __ldg((const float4*)b + lane);
    __half2 o0 = __floats2half2_rn(fmaxf(acc.x + sl * vi0.x + vb.x, 0.f),
                                   fmaxf(acc.y + sl * vi0.y + vb.y, 0.f));
    __half2 o1 = __floats2half2_rn(fmaxf(acc.z + sl * vi1.x + vb.z, 0.f),
                                   fmaxf(acc.w + sl * vi1.y + vb.w, 0.f));
    uint2 o;
    o.x = *(uint32_t*)&o0;
    o.y = *(uint32_t*)&o1;
    ((uint2*)out)[warp * 32 + lane] = o;
}

// ---------------- final aggregation (C=50, half input, no relu) --------------
__global__ __launch_bounds__(256) void k_agg_fin(const __half* __restrict__ h,
                                                 const float* __restrict__ b,
                                                 float* __restrict__ out, int n) {
    int warp = (blockIdx.x * blockDim.x + threadIdx.x) >> 5;
    int lane = threadIdx.x & 31;
    if (warp >= n) return;
    const int i = warp;
    int e = g_rowptr[i];
    const int e1 = g_rowptr[i + 1];
    const int f0 = lane;            // < 32
    const int f1 = lane + 32;       // < 50 for lanes 0..17

    float a0 = 0.f, a1 = 0.f;
    for (; e + 4 <= e1; e += 4) {
        int s0 = g_esrc[e], s1 = g_esrc[e + 1], s2 = g_esrc[e + 2], s3 = g_esrc[e + 3];
        float n0 = g_enorm[e], n1 = g_enorm[e + 1], n2 = g_enorm[e + 2], n3 = g_enorm[e + 3];
        const __half* p0 = h + (size_t)s0 * 64;
        const __half* p1 = h + (size_t)s1 * 64;
        const __half* p2 = h + (size_t)s2 * 64;
        const __half* p3 = h + (size_t)s3 * 64;
        a0 += n0 * __half2float(__ldg(p0 + f0));
        a0 += n1 * __half2float(__ldg(p1 + f0));
        a0 += n2 * __half2float(__ldg(p2 + f0));
        a0 += n3 * __half2float(__ldg(p3 + f0));
        if (f1 < 50) {
            a1 += n0 * __half2float(__ldg(p0 + f1));
            a1 += n1 * __half2float(__ldg(p1 + f1));
            a1 += n2 * __half2float(__ldg(p2 + f1));
            a1 += n3 * __half2float(__ldg(p3 + f1));
        }
    }
    for (; e < e1; e++) {
        int s0 = g_esrc[e];
        float n0 = g_enorm[e];
        const __half* p0 = h + (size_t)s0 * 64;
        a0 += n0 * __half2float(__ldg(p0 + f0));
        if (f1 < 50) a1 += n0 * __half2float(__ldg(p0 + f1));
    }

    float di = g_dinv[i];
    float sl = di * di;
    const __half* hi = h + (size_t)i * 64;
    out[(size_t)i * 50 + f0] = a0 + sl * __half2float(__ldg(hi + f0)) + __ldg(b + f0);
    if (f1 < 50)
        out[(size_t)i * 50 + f1] = a1 + sl * __half2float(__ldg(hi + f1)) + __ldg(b + f1);
}

// ---------------- launch ----------------
extern "C" void kernel_launch(void* const* d_in, const int* in_sizes, int n_in,
                              void* d_out, int out_size) {
    const float* x  = (const float*)d_in[0];
    const void*  ei = d_in[1];
    const float* W1 = (const float*)d_in[2];  const float* b1 = (const float*)d_in[3];
    const float* W2 = (const float*)d_in[4];  const float* b2 = (const float*)d_in[5];
    const float* W3 = (const float*)d_in[6];  const float* b3 = (const float*)d_in[7];
    const float* W4 = (const float*)d_in[8];  const float* b4 = (const float*)d_in[9];
    const float* W5 = (const float*)d_in[10]; const float* b5 = (const float*)d_in[11];

    const int N = in_sizes[0] / 384;
    const int E = in_sizes[1] / 2;

    __half *h, *y, *wt1, *wt2, *wt3, *wt4, *wt5;
    cudaGetSymbolAddress((void**)&h, g_h);
    cudaGetSymbolAddress((void**)&y, g_y);
    cudaGetSymbolAddress((void**)&wt1, g_wt1);
    cudaGetSymbolAddress((void**)&wt2, g_wt2);
    cudaGetSymbolAddress((void**)&wt3, g_wt3);
    cudaGetSymbolAddress((void**)&wt4, g_wt4);
    cudaGetSymbolAddress((void**)&wt5, g_wt5);

    const int T = 256;
    const int gN = (N + T - 1) / T;
    const int gE = (E + T - 1) / T;
    const int nb = (N + 1023) / 1024;
    const int gm = (N + 127) / 128;
    const int ga = (N + 7) / 8;

    const int smemCVT  = 2 * (128 + 128) * 40 * 2;  // 40960
    const int smemF128 = (128 + 128) * 136 * 2;     // 69632
    const int smemF64  = (128 + 64) * 136 * 2;      // 52224
    cudaFuncSetAttribute(k_gemm_cvt<384, 128, 128>,
                         cudaFuncAttributeMaxDynamicSharedMemorySize, smemCVT);
    cudaFuncSetAttribute(k_gemm_flat<128, 128>,
                         cudaFuncAttributeMaxDynamicSharedMemorySize, smemF128);
    cudaFuncSetAttribute(k_gemm_flat<64, 64>,
                         cudaFuncAttributeMaxDynamicSharedMemorySize, smemF64);

    // launch order keeps GEMM1 at launch index 3 (ncu capture slot)
    k_init<<<gN, T>>>(ei, E, (long long)N, N);
    k_wtrans_all<<<(106496 + 255) / 256, T>>>(W1, W2, W3, W4, W5);
    k_hist<<<gE, T>>>(ei, E);
    k_gemm_cvt<384, 128, 128><<<gm, T, smemCVT>>>(x, wt1, h, N);   // GEMM1 (+cvt)
    k_scan1<<<nb, 1024>>>(N);
    k_scan2<<<1, 256>>>(nb, N);
    k_scan3<<<gN, T>>>(N);
    k_scatter<<<gE, T>>>(ei, E);

    // layer 1 aggregation (half gathers -> fp16 y)
    k_agg128<<<ga, T>>>(h, b1, y, N);
    // layers 2-4 (flat GEMMs)
    k_gemm_flat<128, 128><<<gm, T, smemF128>>>(y, wt2, h, N);
    k_agg128<<<ga, T>>>(h, b2, y, N);
    k_gemm_flat<128, 128><<<gm, T, smemF128>>>(y, wt3, h, N);
    k_agg128<<<ga, T>>>(h, b3, y, N);
    k_gemm_flat<128, 128><<<gm, T, smemF128>>>(y, wt4, h, N);
    k_agg128<<<ga, T>>>(h, b4, y, N);
    // layer 5: 128 -> 50 (64 padded cols), then final aggregation
    k_gemm_flat<64, 64><<<gm, T, smemF64>>>(y, wt5, h, N);
    k_agg_fin<<<ga, T>>>(h, b5, (float*)d_out, N);
}

// round 13
// speedup vs baseline: 1.1281x; 1.0483x over previous
#include <cuda_runtime.h>
#include <cuda_fp16.h>
#include <cstdint>

#define N_NODES_MAX 100000
#define N_EDGES_MAX 1600000

// ---------------- device scratch (no allocations allowed) ----------------
__device__ __half g_h[(size_t)N_NODES_MAX * 128];   // GEMM output (fp16, gathered)
__device__ __half g_y[(size_t)N_NODES_MAX * 128];   // agg output (fp16, GEMM A)
__device__ float g_dinv[N_NODES_MAX];
__device__ int   g_count[N_NODES_MAX];
__device__ int   g_fill[N_NODES_MAX];
__device__ int   g_rowptr[N_NODES_MAX + 1];
__device__ uint2 g_epk[N_EDGES_MAX];                // packed (src, norm-bits)
__device__ int   g_bsums[256];
__device__ int   g_is32;
// transposed fp16 weights: WT[n][k]
__device__ __half g_wt1[128 * 384];
__device__ __half g_wt2[128 * 128];
__device__ __half g_wt3[128 * 128];
__device__ __half g_wt4[128 * 128];
__device__ __half g_wt5[64 * 128];

// ---------------- helpers ----------------
__device__ __forceinline__ int edge_val(const void* ei, int is32, long long idx) {
    if (is32) return ((const int*)ei)[idx];
    return (int)((const long long*)ei)[idx];
}
__device__ __forceinline__ void cp_async16(uint32_t dst, const void* src, int srcsize) {
    asm volatile("cp.async.ca.shared.global [%0], [%1], 16, %2;"
                 :: "r"(dst), "l"(src), "r"(srcsize));
}
__device__ __forceinline__ void cp_commit() { asm volatile("cp.async.commit_group;"); }
template<int N>
__device__ __forceinline__ void cp_wait() { asm volatile("cp.async.wait_group %0;" :: "n"(N)); }

__device__ __forceinline__ void ldsm_x4(uint32_t& r0, uint32_t& r1, uint32_t& r2, uint32_t& r3,
                                        uint32_t addr) {
    asm volatile("ldmatrix.sync.aligned.m8n8.x4.shared.b16 {%0,%1,%2,%3}, [%4];"
                 : "=r"(r0), "=r"(r1), "=r"(r2), "=r"(r3) : "r"(addr));
}

// ---------------- preprocessing kernels ----------------
__global__ void k_init(const void* ei, int E, long long N, int n) {
    int i = blockIdx.x * blockDim.x + threadIdx.x;
    if (i < n) { g_count[i] = 0; g_fill[i] = 0; }
    if (i == 0) {
        const long long* p = (const long long*)ei;
        int is32 = 0;
        for (int j = 0; j < 64 && j < E; j++) {
            long long v = p[j];
            if (v < 0 || v >= N) { is32 = 1; break; }
        }
        g_is32 = is32;
    }
}

__global__ void k_hist(const void* __restrict__ ei, int E) {
    int e = blockIdx.x * blockDim.x + threadIdx.x;
    if (e >= E) return;
    int is32 = g_is32;
    int d = edge_val(ei, is32, (long long)E + e);
    atomicAdd(&g_count[d], 1);
}

// scan over counts; also computes dinv (fused)
__global__ void k_scan1(int n) {
    __shared__ int s[1024];
    int t = threadIdx.x;
    int i = blockIdx.x * 1024 + t;
    int v = (i < n) ? g_count[i] : 0;
    if (i < n) g_dinv[i] = rsqrtf((float)v + 1.0f);
    s[t] = v;
    __syncthreads();
    #pragma unroll
    for (int off = 1; off < 1024; off <<= 1) {
        int x = (t >= off) ? s[t - off] : 0;
        __syncthreads();
        s[t] += x;
        __syncthreads();
    }
    if (i < n) g_rowptr[i] = s[t] - v;
    if (t == 1023) g_bsums[blockIdx.x] = s[1023];
}

// parallel block-sum scan (256 threads; nb <= 256)
__global__ void k_scan2(int nb, int n) {
    __shared__ int s[256];
    int t = threadIdx.x;
    int v = (t < nb) ? g_bsums[t] : 0;
    s[t] = v;
    __syncthreads();
    #pragma unroll
    for (int off = 1; off < 256; off <<= 1) {
        int x = (t >= off) ? s[t - off] : 0;
        __syncthreads();
        s[t] += x;
        __syncthreads();
    }
    if (t < nb) g_bsums[t] = s[t] - v;   // exclusive block offsets
    if (t == 255) g_rowptr[n] = s[255];
}

__global__ void k_scan3(int n) {
    int i = blockIdx.x * blockDim.x + threadIdx.x;
    if (i < n) g_rowptr[i] += g_bsums[i >> 10];
}

__global__ void k_scatter(const void* __restrict__ ei, int E) {
    int e = blockIdx.x * blockDim.x + threadIdx.x;
    if (e >= E) return;
    int is32 = g_is32;
    int s = edge_val(ei, is32, e);
    int d = edge_val(ei, is32, (long long)E + e);
    int pos = g_rowptr[d] + atomicAdd(&g_fill[d], 1);
    g_epk[pos] = make_uint2((unsigned)s, __float_as_uint(g_dinv[s] * g_dinv[d]));
}

// ---------------- all weight transposes (fp16) in one kernel ----------------
__global__ void k_wtrans_all(const float* __restrict__ W1, const float* __restrict__ W2,
                             const float* __restrict__ W3, const float* __restrict__ W4,
                             const float* __restrict__ W5) {
    int idx = blockIdx.x * 256 + threadIdx.x;
    if (idx < 49152) {                       // wt1: [128][384] from W1[384][128]
        int n = idx / 384, k = idx % 384;
        g_wt1[idx] = __float2half_rn(W1[(size_t)k * 128 + n]);
    } else if (idx < 49152 + 16384) {        // wt2
        int j = idx - 49152; int n = j / 128, k = j % 128;
        g_wt2[j] = __float2half_rn(W2[(size_t)k * 128 + n]);
    } else if (idx < 49152 + 32768) {        // wt3
        int j = idx - 49152 - 16384; int n = j / 128, k = j % 128;
        g_wt3[j] = __float2half_rn(W3[(size_t)k * 128 + n]);
    } else if (idx < 49152 + 49152) {        // wt4
        int j = idx - 49152 - 32768; int n = j / 128, k = j % 128;
        g_wt4[j] = __float2half_rn(W4[(size_t)k * 128 + n]);
    } else if (idx < 49152 + 49152 + 8192) { // wt5: [64][128] from W5[128][50]
        int j = idx - 49152 - 49152; int n = j / 128, k = j % 128;
        g_wt5[j] = (n < 50) ? __float2half_rn(W5[(size_t)k * 50 + n]) : __float2half_rn(0.f);
    }
}

// ---------------- GEMM1: fp32 A (fused cvt), 2-stage smem, single reg buffer --
template<int KT, int BN, int SC>
__global__ __launch_bounds__(256, 2) void k_gemm_cvt(const float* __restrict__ A32,
                                                     const __half* __restrict__ WT,
                                                     __half* __restrict__ C, int M) {
    constexpr int BM = 128, BKH = 32;
    constexpr int WTN = BN / 4;
    constexpr int NTL = WTN / 8;
    constexpr int LDR = BKH + 8;            // 40 halves = 80B rows
    constexpr int NK  = KT / BKH;
    constexpr int AST = BM * LDR;
    constexpr int WST = BN * LDR;
    constexpr int WCH = BN * 4 / 256;

    extern __shared__ __half smem[];
    __half* Abase = smem;                    // 2 stages
    __half* Wbase = smem + 2 * AST;

    const int tid = threadIdx.x;
    const int wid = tid >> 5;
    const int lane = tid & 31;
    const int g = lane >> 2;
    const int t = lane & 3;
    const int warp_m = wid >> 2;
    const int warp_n = wid & 3;
    const int row0 = blockIdx.x * BM;

    const uint32_t sA = (uint32_t)__cvta_generic_to_shared(Abase);
    const uint32_t sW = (uint32_t)__cvta_generic_to_shared(Wbase);

    float acc[4][NTL][4];
    #pragma unroll
    for (int i = 0; i < 4; i++)
        #pragma unroll
        for (int j = 0; j < NTL; j++)
            #pragma unroll
            for (int r = 0; r < 4; r++) acc[i][j][r] = 0.f;

    float4 pa[4];

    auto cpW = [&](int i, int st) {
        const int kb = i * BKH;
        #pragma unroll
        for (int j = 0; j < WCH; j++) {
            int idx = tid + j * 256;
            int n = idx >> 2, ch = idx & 3;
            cp_async16(sW + (uint32_t)((st * WST + n * LDR + ch * 8) * 2),
                       WT + (size_t)n * KT + kb + ch * 8, 16);
        }
    };
    auto ldA = [&](int i) {
        const int kb = i * BKH;
        #pragma unroll
        for (int j = 0; j < 4; j++) {
            int idx = tid + j * 256;
            int r = idx >> 3, c4 = idx & 7;
            int grow = row0 + r;
            pa[j] = (grow < M)
                ? __ldg((const float4*)(A32 + (size_t)grow * KT + kb + c4 * 4))
                : make_float4(0.f, 0.f, 0.f, 0.f);
        }
    };
    auto stsA = [&](int st) {
        #pragma unroll
        for (int j = 0; j < 4; j++) {
            int idx = tid + j * 256;
            int r = idx >> 3, c4 = idx & 7;
            __half2 h0 = __floats2half2_rn(pa[j].x, pa[j].y);
            __half2 h1 = __floats2half2_rn(pa[j].z, pa[j].w);
            uint2 u;
            u.x = *(uint32_t*)&h0;
            u.y = *(uint32_t*)&h1;
            *(uint2*)(Abase + st * AST + r * LDR + c4 * 4) = u;
        }
    };
    auto compute = [&](int st) {
        #pragma unroll
        for (int ks = 0; ks < 2; ks++) {
            const int k16 = ks * 16;
            uint32_t bf[NTL][2];
            #pragma unroll
            for (int np = 0; np < NTL / 2; np++) {
                int n0 = warp_n * WTN + np * 16;
                uint32_t ad = sW + (uint32_t)(((st * WST) +
                              (n0 + (lane & 7) + ((lane >> 4) & 1) * 8) * LDR +
                              k16 + ((lane >> 3) & 1) * 8) * 2);
                ldsm_x4(bf[2 * np][0], bf[2 * np][1], bf[2 * np + 1][0], bf[2 * np + 1][1], ad);
            }
            #pragma unroll
            for (int mt = 0; mt < 4; mt++) {
                int mb = warp_m * 64 + mt * 16;
                uint32_t ad = sA + (uint32_t)(((st * AST) +
                              (mb + (lane & 15)) * LDR + k16 + (lane >> 4) * 8) * 2);
                uint32_t a0, a1, a2, a3;
                ldsm_x4(a0, a1, a2, a3, ad);
                #pragma unroll
                for (int nt = 0; nt < NTL; nt++) {
                    asm volatile(
                        "mma.sync.aligned.m16n8k16.row.col.f32.f16.f16.f32 "
                        "{%0,%1,%2,%3}, {%4,%5,%6,%7}, {%8,%9}, {%0,%1,%2,%3};"
                        : "+f"(acc[mt][nt][0]), "+f"(acc[mt][nt][1]),
                          "+f"(acc[mt][nt][2]), "+f"(acc[mt][nt][3])
                        : "r"(a0), "r"(a1), "r"(a2), "r"(a3),
                          "r"(bf[nt][0]), "r"(bf[nt][1]));
                }
            }
        }
    };

    ldA(0);
    cpW(0, 0); cp_commit();
    stsA(0);
    ldA(1);
    cpW(1, 1); cp_commit();
    cp_wait<1>();
    __syncthreads();

    for (int i = 0; i < NK; i++) {
        const int st = i & 1;
        compute(st);
        __syncthreads();                       // stage st fully consumed
        if (i + 1 < NK) stsA((i + 1) & 1);     // A(i+1) regs -> other stage
        if (i + 2 < NK) { ldA(i + 2); cpW(i + 2, st); }
        cp_commit();
        cp_wait<1>();
        __syncthreads();
    }

    // ---- epilogue: stage C in smem, coalesced STG.128 ----
    __syncthreads();
    constexpr int CLDR = BN + 8;
    __half* Cs = smem;
    #pragma unroll
    for (int mt = 0; mt < 4; mt++) {
        int rl = warp_m * 64 + mt * 16 + g;
        #pragma unroll
        for (int nt = 0; nt < NTL; nt++) {
            int col = warp_n * WTN + nt * 8 + t * 2;
            *(__half2*)(Cs + rl * CLDR + col) =
                __floats2half2_rn(acc[mt][nt][0], acc[mt][nt][1]);
            *(__half2*)(Cs + (rl + 8) * CLDR + col) =
                __floats2half2_rn(acc[mt][nt][2], acc[mt][nt][3]);
        }
    }
    __syncthreads();
    constexpr int CH8 = BN / 8;
    #pragma unroll
    for (int j = 0; j < (BM * CH8) / 256; j++) {
        int idx = tid + j * 256;
        int r = idx / CH8, c8 = idx % CH8;
        int grow = row0 + r;
        if (grow < M)
            *(uint4*)(C + (size_t)grow * SC + c8 * 8) = *(uint4*)(Cs + r * CLDR + c8 * 8);
    }
}

// ---------------- flat fp16 GEMM (K=128): one smem fill, zero in-loop syncs ---
template<int BN, int SC>
__global__ __launch_bounds__(256, 2) void k_gemm_flat(const __half* __restrict__ A,
                                                      const __half* __restrict__ WT,
                                                      __half* __restrict__ C, int M) {
    constexpr int KT = 128, BM = 128;
    constexpr int WTN = BN / 4;
    constexpr int NTL = WTN / 8;
    constexpr int LDR = KT + 8;             // 136 halves = 272B rows, conflict-free
    constexpr int WCH = BN * 16 / 256;      // W 16B-chunks per thread (8 or 4)

    extern __shared__ __half smem[];
    __half* As = smem;                      // [BM][LDR]
    __half* Ws = smem + BM * LDR;           // [BN][LDR]

    const int tid = threadIdx.x;
    const int wid = tid >> 5;
    const int lane = tid & 31;
    const int g = lane >> 2;
    const int t = lane & 3;
    const int warp_m = wid >> 2;
    const int warp_n = wid & 3;
    const int row0 = blockIdx.x * BM;

    const uint32_t sA = (uint32_t)__cvta_generic_to_shared(As);
    const uint32_t sW = (uint32_t)__cvta_generic_to_shared(Ws);

    // ---- single cp.async burst: whole A tile + whole W ----
    #pragma unroll
    for (int j = 0; j < 8; j++) {                   // A: 128 rows x 16 chunks
        int idx = tid + j * 256;
        int r = idx >> 4, ch = idx & 15;
        int grow = row0 + r;
        cp_async16(sA + (uint32_t)((r * LDR + ch * 8) * 2),
                   A + (size_t)grow * KT + ch * 8, grow < M ? 16 : 0);
    }
    #pragma unroll
    for (int j = 0; j < WCH; j++) {                 // W: BN rows x 16 chunks
        int idx = tid + j * 256;
        int r = idx >> 4, ch = idx & 15;
        cp_async16(sW + (uint32_t)((r * LDR + ch * 8) * 2),
                   WT + (size_t)r * KT + ch * 8, 16);
    }
    cp_commit();

    float acc[4][NTL][4];
    #pragma unroll
    for (int i = 0; i < 4; i++)
        #pragma unroll
        for (int j = 0; j < NTL; j++)
            #pragma unroll
            for (int r = 0; r < 4; r++) acc[i][j][r] = 0.f;

    cp_wait<0>();
    __syncthreads();

    // ---- 8 uninterrupted k16 steps ----
    #pragma unroll
    for (int ks = 0; ks < 8; ks++) {
        const int k16 = ks * 16;
        uint32_t bf[NTL][2];
        #pragma unroll
        for (int np = 0; np < NTL / 2; np++) {
            int n0 = warp_n * WTN + np * 16;
            uint32_t ad = sW + (uint32_t)(((n0 + (lane & 7) + ((lane >> 4) & 1) * 8) * LDR +
                          k16 + ((lane >> 3) & 1) * 8) * 2);
            ldsm_x4(bf[2 * np][0], bf[2 * np][1], bf[2 * np + 1][0], bf[2 * np + 1][1], ad);
        }
        #pragma unroll
        for (int mt = 0; mt < 4; mt++) {
            int mb = warp_m * 64 + mt * 16;
            uint32_t ad = sA + (uint32_t)(((mb + (lane & 15)) * LDR + k16 + (lane >> 4) * 8) * 2);
            uint32_t a0, a1, a2, a3;
            ldsm_x4(a0, a1, a2, a3, ad);
            #pragma unroll
            for (int nt = 0; nt < NTL; nt++) {
                asm volatile(
                    "mma.sync.aligned.m16n8k16.row.col.f32.f16.f16.f32 "
                    "{%0,%1,%2,%3}, {%4,%5,%6,%7}, {%8,%9}, {%0,%1,%2,%3};"
                    : "+f"(acc[mt][nt][0]), "+f"(acc[mt][nt][1]),
                      "+f"(acc[mt][nt][2]), "+f"(acc[mt][nt][3])
                    : "r"(a0), "r"(a1), "r"(a2), "r"(a3),
                      "r"(bf[nt][0]), "r"(bf[nt][1]));
            }
        }
    }

    // ---- epilogue: stage C in smem, coalesced STG.128 ----
    __syncthreads();
    constexpr int CLDR = BN + 8;
    __half* Cs = smem;
    #pragma unroll
    for (int mt = 0; mt < 4; mt++) {
        int rl = warp_m * 64 + mt * 16 + g;
        #pragma unroll
        for (int nt = 0; nt < NTL; nt++) {
            int col = warp_n * WTN + nt * 8 + t * 2;
            *(__half2*)(Cs + rl * CLDR + col) =
                __floats2half2_rn(acc[mt][nt][0], acc[mt][nt][1]);
            *(__half2*)(Cs + (rl + 8) * CLDR + col) =
                __floats2half2_rn(acc[mt][nt][2], acc[mt][nt][3]);
        }
    }
    __syncthreads();
    constexpr int CH8 = BN / 8;
    #pragma unroll
    for (int j = 0; j < (BM * CH8) / 256; j++) {
        int idx = tid + j * 256;
        int r = idx / CH8, c8 = idx % CH8;
        int grow = row0 + r;
        if (grow < M)
            *(uint4*)(C + (size_t)grow * SC + c8 * 8) = *(uint4*)(Cs + r * CLDR + c8 * 8);
    }
}

// ---------------- aggregation (C=128): warp per node, packed edges -----------
__global__ __launch_bounds__(256) void k_agg128(const __half* __restrict__ hin,
                                                const float* __restrict__ b,
                                                __half* __restrict__ out, int n) {
    int warp = (blockIdx.x * blockDim.x + threadIdx.x) >> 5;
    int lane = threadIdx.x & 31;
    if (warp >= n) return;
    const uint2* __restrict__ h2 = (const uint2*)hin;   // 4 halves per uint2; 32/row
    int e = g_rowptr[warp];
    const int e1 = g_rowptr[warp + 1];

    float4 acc = make_float4(0.f, 0.f, 0.f, 0.f);

    for (; e + 8 <= e1; e += 8) {
        uint2 p[8]; uint2 v[8];
        #pragma unroll
        for (int j = 0; j < 8; j++) p[j] = __ldg(g_epk + e + j);
        #pragma unroll
        for (int j = 0; j < 8; j++) v[j] = __ldg(h2 + p[j].x * 32 + lane);
        #pragma unroll
        for (int j = 0; j < 8; j++) {
            float w = __uint_as_float(p[j].y);
            float2 f0 = __half22float2(*(__half2*)&v[j].x);
            float2 f1 = __half22float2(*(__half2*)&v[j].y);
            acc.x += w * f0.x; acc.y += w * f0.y;
            acc.z += w * f1.x; acc.w += w * f1.y;
        }
    }
    for (; e < e1; e++) {
        uint2 p = __ldg(g_epk + e);
        float w = __uint_as_float(p.y);
        uint2 v0 = __ldg(h2 + p.x * 32 + lane);
        float2 f0 = __half22float2(*(__half2*)&v0.x);
        float2 f1 = __half22float2(*(__half2*)&v0.y);
        acc.x += w * f0.x; acc.y += w * f0.y;
        acc.z += w * f1.x; acc.w += w * f1.y;
    }

    float di = g_dinv[warp];
    float sl = di * di;
    uint2 vr = __ldg(h2 + warp * 32 + lane);
    float2 vi0 = __half22float2(*(__half2*)&vr.x);
    float2 vi1 = __half22float2(*(__half2*)&vr.y);
    float4 vb = __ldg((const float4*)b + lane);
    __half2 o0 = __floats2half2_rn(fmaxf(acc.x + sl * vi0.x + vb.x, 0.f),
                                   fmaxf(acc.y + sl * vi0.y + vb.y, 0.f));
    __half2 o1 = __floats2half2_rn(fmaxf(acc.z + sl * vi1.x + vb.z, 0.f),
                                   fmaxf(acc.w + sl * vi1.y + vb.w, 0.f));
    uint2 o;
    o.x = *(uint32_t*)&o0;
    o.y = *(uint32_t*)&o1;
    ((uint2*)out)[warp * 32 + lane] = o;
}

// ---------------- final aggregation (C=50, half input, no relu) --------------
__global__ __launch_bounds__(256) void k_agg_fin(const __half* __restrict__ h,
                                                 const float* __restrict__ b,
                                                 float* __restrict__ out, int n) {
    int warp = (blockIdx.x * blockDim.x + threadIdx.x) >> 5;
    int lane = threadIdx.x & 31;
    if (warp >= n) return;
    const int i = warp;
    int e = g_rowptr[i];
    const int e1 = g_rowptr[i + 1];
    const int f0 = lane;            // < 32
    const int f1 = lane + 32;       // < 50 for lanes 0..17

    float a0 = 0.f, a1 = 0.f;
    for (; e + 4 <= e1; e += 4) {
        uint2 p0 = __ldg(g_epk + e),     p1 = __ldg(g_epk + e + 1);
        uint2 p2 = __ldg(g_epk + e + 2), p3 = __ldg(g_epk + e + 3);
        float n0 = __uint_as_float(p0.y), n1 = __uint_as_float(p1.y);
        float n2 = __uint_as_float(p2.y), n3 = __uint_as_float(p3.y);
        const __half* q0 = h + (size_t)p0.x * 64;
        const __half* q1 = h + (size_t)p1.x * 64;
        const __half* q2 = h + (size_t)p2.x * 64;
        const __half* q3 = h + (size_t)p3.x * 64;
        a0 += n0 * __half2float(__ldg(q0 + f0));
        a0 += n1 * __half2float(__ldg(q1 + f0));
        a0 += n2 * __half2float(__ldg(q2 + f0));
        a0 += n3 * __half2float(__ldg(q3 + f0));
        if (f1 < 50) {
            a1 += n0 * __half2float(__ldg(q0 + f1));
            a1 += n1 * __half2float(__ldg(q1 + f1));
            a1 += n2 * __half2float(__ldg(q2 + f1));
            a1 += n3 * __half2float(__ldg(q3 + f1));
        }
    }
    for (; e < e1; e++) {
        uint2 p = __ldg(g_epk + e);
        float n0 = __uint_as_float(p.y);
        const __half* q0 = h + (size_t)p.x * 64;
        a0 += n0 * __half2float(__ldg(q0 + f0));
        if (f1 < 50) a1 += n0 * __half2float(__ldg(q0 + f1));
    }

    float di = g_dinv[i];
    float sl = di * di;
    const __half* hi = h + (size_t)i * 64;
    out[(size_t)i * 50 + f0] = a0 + sl * __half2float(__ldg(hi + f0)) + __ldg(b + f0);
    if (f1 < 50)
        out[(size_t)i * 50 + f1] = a1 + sl * __half2float(__ldg(hi + f1)) + __ldg(b + f1);
}

// ---------------- launch ----------------
extern "C" void kernel_launch(void* const* d_in, const int* in_sizes, int n_in,
                              void* d_out, int out_size) {
    const float* x  = (const float*)d_in[0];
    const void*  ei = d_in[1];
    const float* W1 = (const float*)d_in[2];  const float* b1 = (const float*)d_in[3];
    const float* W2 = (const float*)d_in[4];  const float* b2 = (const float*)d_in[5];
    const float* W3 = (const float*)d_in[6];  const float* b3 = (const float*)d_in[7];
    const float* W4 = (const float*)d_in[8];  const float* b4 = (const float*)d_in[9];
    const float* W5 = (const float*)d_in[10]; const float* b5 = (const float*)d_in[11];

    const int N = in_sizes[0] / 384;
    const int E = in_sizes[1] / 2;

    __half *h, *y, *wt1, *wt2, *wt3, *wt4, *wt5;
    cudaGetSymbolAddress((void**)&h, g_h);
    cudaGetSymbolAddress((void**)&y, g_y);
    cudaGetSymbolAddress((void**)&wt1, g_wt1);
    cudaGetSymbolAddress((void**)&wt2, g_wt2);
    cudaGetSymbolAddress((void**)&wt3, g_wt3);
    cudaGetSymbolAddress((void**)&wt4, g_wt4);
    cudaGetSymbolAddress((void**)&wt5, g_wt5);

    const int T = 256;
    const int gN = (N + T - 1) / T;
    const int gE = (E + T - 1) / T;
    const int nb = (N + 1023) / 1024;
    const int gm = (N + 127) / 128;
    const int ga = (N + 7) / 8;

    const int smemCVT  = 2 * (128 + 128) * 40 * 2;  // 40960
    const int smemF128 = (128 + 128) * 136 * 2;     // 69632
    const int smemF64  = (128 + 64) * 136 * 2;      // 52224
    cudaFuncSetAttribute(k_gemm_cvt<384, 128, 128>,
                         cudaFuncAttributeMaxDynamicSharedMemorySize, smemCVT);
    cudaFuncSetAttribute(k_gemm_flat<128, 128>,
                         cudaFuncAttributeMaxDynamicSharedMemorySize, smemF128);
    cudaFuncSetAttribute(k_gemm_flat<64, 64>,
                         cudaFuncAttributeMaxDynamicSharedMemorySize, smemF64);

    // lazily-created side stream + fork/join events (host handles only; no
    // device allocations). Created once; reused by every capture.
    static cudaStream_t s2 = nullptr;
    static cudaEvent_t evFork = nullptr, evJoin = nullptr;
    if (s2 == nullptr) {
        cudaStreamCreateWithFlags(&s2, cudaStreamNonBlocking);
        cudaEventCreateWithFlags(&evFork, cudaEventDisableTiming);
        cudaEventCreateWithFlags(&evJoin, cudaEventDisableTiming);
    }

    // ---- fork: CSR build on s2, GEMM1 path on main stream ----
    cudaEventRecord(evFork, 0);
    cudaStreamWaitEvent(s2, evFork, 0);

    k_init<<<gN, T, 0, s2>>>(ei, E, (long long)N, N);
    k_hist<<<gE, T, 0, s2>>>(ei, E);
    k_scan1<<<nb, 1024, 0, s2>>>(N);
    k_scan2<<<1, 256, 0, s2>>>(nb, N);
    k_scan3<<<gN, T, 0, s2>>>(N);
    k_scatter<<<gE, T, 0, s2>>>(ei, E);
    cudaEventRecord(evJoin, s2);

    k_wtrans_all<<<(106496 + 255) / 256, T>>>(W1, W2, W3, W4, W5);
    k_gemm_cvt<384, 128, 128><<<gm, T, smemCVT>>>(x, wt1, h, N);   // GEMM1 (+cvt)

    // ---- join: aggregation needs both GEMM1 output and the CSR ----
    cudaStreamWaitEvent(0, evJoin, 0);

    // layer 1 aggregation (half gathers -> fp16 y)
    k_agg128<<<ga, T>>>(h, b1, y, N);
    // layers 2-4 (flat GEMMs)
    k_gemm_flat<128, 128><<<gm, T, smemF128>>>(y, wt2, h, N);
    k_agg128<<<ga, T>>>(h, b2, y, N);
    k_gemm_flat<128, 128><<<gm, T, smemF128>>>(y, wt3, h, N);
    k_agg128<<<ga, T>>>(h, b3, y, N);
    k_gemm_flat<128, 128><<<gm, T, smemF128>>>(y, wt4, h, N);
    k_agg128<<<ga, T>>>(h, b4, y, N);
    // layer 5: 128 -> 50 (64 padded cols), then final aggregation
    k_gemm_flat<64, 64><<<gm, T, smemF64>>>(y, wt5, h, N);
    k_agg_fin<<<ga, T>>>(h, b5, (float*)d_out, N);
}

// round 14
// speedup vs baseline: 1.1372x; 1.0081x over previous
#include <cuda_runtime.h>
#include <cuda_fp16.h>
#include <cstdint>

#define N_NODES_MAX 100000
#define N_EDGES_MAX 1600000

// ---------------- device scratch (no allocations allowed) ----------------
__device__ __half g_h[(size_t)N_NODES_MAX * 128];   // GEMM output (fp16, gathered)
__device__ __half g_y[(size_t)N_NODES_MAX * 128];   // agg output (fp16, GEMM A)
__device__ float g_dinv[N_NODES_MAX];
__device__ int   g_count[N_NODES_MAX];
__device__ int   g_fill[N_NODES_MAX];
__device__ int   g_rowptr[N_NODES_MAX + 1];
__device__ uint2 g_epk[N_EDGES_MAX];                // packed (src, norm-bits)
__device__ int   g_bsums[256];
__device__ int   g_is32;
// transposed fp16 weights: WT[n][k]
__device__ __half g_wt1[128 * 384];
__device__ __half g_wt2[128 * 128];
__device__ __half g_wt3[128 * 128];
__device__ __half g_wt4[128 * 128];
__device__ __half g_wt5[64 * 128];

// ---------------- helpers ----------------
__device__ __forceinline__ int edge_val(const void* ei, int is32, long long idx) {
    if (is32) return ((const int*)ei)[idx];
    return (int)((const long long*)ei)[idx];
}
__device__ __forceinline__ void cp_async16(uint32_t dst, const void* src, int srcsize) {
    asm volatile("cp.async.ca.shared.global [%0], [%1], 16, %2;"
                 :: "r"(dst), "l"(src), "r"(srcsize));
}
__device__ __forceinline__ void cp_commit() { asm volatile("cp.async.commit_group;"); }
template<int N>
__device__ __forceinline__ void cp_wait() { asm volatile("cp.async.wait_group %0;" :: "n"(N)); }

__device__ __forceinline__ void ldsm_x4(uint32_t& r0, uint32_t& r1, uint32_t& r2, uint32_t& r3,
                                        uint32_t addr) {
    asm volatile("ldmatrix.sync.aligned.m8n8.x4.shared.b16 {%0,%1,%2,%3}, [%4];"
                 : "=r"(r0), "=r"(r1), "=r"(r2), "=r"(r3) : "r"(addr));
}

// ---------------- preprocessing kernels ----------------
__global__ void k_init(const void* ei, int E, long long N, int n) {
    int i = blockIdx.x * blockDim.x + threadIdx.x;
    if (i < n) g_count[i] = 0;
    if (i == 0) {
        const long long* p = (const long long*)ei;
        int is32 = 0;
        for (int j = 0; j < 64 && j < E; j++) {
            long long v = p[j];
            if (v < 0 || v >= N) { is32 = 1; break; }
        }
        g_is32 = is32;
    }
}

// histogram over dst; 2 edges per thread with vector loads (E assumed even for
// the vector path; scalar tail otherwise)
__global__ void k_hist(const void* __restrict__ ei, int E) {
    int i = blockIdx.x * blockDim.x + threadIdx.x;
    int e = i * 2;
    if (e >= E) return;
    int is32 = g_is32;
    int d0, d1 = -1;
    bool pair = (e + 1 < E) && ((E & 1) == 0);
    if (pair) {
        if (is32) {
            int2 v = *(const int2*)((const int*)ei + (size_t)E + e);
            d0 = v.x; d1 = v.y;
        } else {
            longlong2 v = *(const longlong2*)((const long long*)ei + (size_t)E + e);
            d0 = (int)v.x; d1 = (int)v.y;
        }
    } else {
        d0 = edge_val(ei, is32, (long long)E + e);
        if (e + 1 < E) d1 = edge_val(ei, is32, (long long)E + e + 1);
    }
    atomicAdd(&g_count[d0], 1);
    if (d1 >= 0) atomicAdd(&g_count[d1], 1);
}

// scan over counts; also computes dinv (fused)
__global__ void k_scan1(int n) {
    __shared__ int s[1024];
    int t = threadIdx.x;
    int i = blockIdx.x * 1024 + t;
    int v = (i < n) ? g_count[i] : 0;
    if (i < n) g_dinv[i] = rsqrtf((float)v + 1.0f);
    s[t] = v;
    __syncthreads();
    #pragma unroll
    for (int off = 1; off < 1024; off <<= 1) {
        int x = (t >= off) ? s[t - off] : 0;
        __syncthreads();
        s[t] += x;
        __syncthreads();
    }
    if (i < n) g_rowptr[i] = s[t] - v;
    if (t == 1023) g_bsums[blockIdx.x] = s[1023];
}

// parallel block-sum scan (256 threads; nb <= 256)
__global__ void k_scan2(int nb, int n) {
    __shared__ int s[256];
    int t = threadIdx.x;
    int v = (t < nb) ? g_bsums[t] : 0;
    s[t] = v;
    __syncthreads();
    #pragma unroll
    for (int off = 1; off < 256; off <<= 1) {
        int x = (t >= off) ? s[t - off] : 0;
        __syncthreads();
        s[t] += x;
        __syncthreads();
    }
    if (t < nb) g_bsums[t] = s[t] - v;   // exclusive block offsets
    if (t == 255) g_rowptr[n] = s[255];
}

// add block offsets; also zero g_fill (needed before scatter)
__global__ void k_scan3(int n) {
    int i = blockIdx.x * blockDim.x + threadIdx.x;
    if (i < n) {
        g_rowptr[i] += g_bsums[i >> 10];
        g_fill[i] = 0;
    }
}

// scatter edges into CSR; 2 edges per thread with vector loads
__global__ void k_scatter(const void* __restrict__ ei, int E) {
    int i = blockIdx.x * blockDim.x + threadIdx.x;
    int e = i * 2;
    if (e >= E) return;
    int is32 = g_is32;
    int s0, d0, s1 = -1, d1 = -1;
    bool pair = (e + 1 < E) && ((E & 1) == 0);
    if (pair) {
        if (is32) {
            int2 vs = *(const int2*)((const int*)ei + e);
            int2 vd = *(const int2*)((const int*)ei + (size_t)E + e);
            s0 = vs.x; s1 = vs.y; d0 = vd.x; d1 = vd.y;
        } else {
            longlong2 vs = *(const longlong2*)((const long long*)ei + e);
            longlong2 vd = *(const longlong2*)((const long long*)ei + (size_t)E + e);
            s0 = (int)vs.x; s1 = (int)vs.y; d0 = (int)vd.x; d1 = (int)vd.y;
        }
    } else {
        s0 = edge_val(ei, is32, e);
        d0 = edge_val(ei, is32, (long long)E + e);
        if (e + 1 < E) {
            s1 = edge_val(ei, is32, e + 1);
            d1 = edge_val(ei, is32, (long long)E + e + 1);
        }
    }
    {
        int pos = g_rowptr[d0] + atomicAdd(&g_fill[d0], 1);
        g_epk[pos] = make_uint2((unsigned)s0, __float_as_uint(g_dinv[s0] * g_dinv[d0]));
    }
    if (s1 >= 0) {
        int pos = g_rowptr[d1] + atomicAdd(&g_fill[d1], 1);
        g_epk[pos] = make_uint2((unsigned)s1, __float_as_uint(g_dinv[s1] * g_dinv[d1]));
    }
}

// ---------------- weight transposes (fp16) ----------------
// wt1 only (needed by GEMM1, main stream)
__global__ void k_wtrans1(const float* __restrict__ W1) {
    int idx = blockIdx.x * 256 + threadIdx.x;
    if (idx < 49152) {
        int n = idx / 384, k = idx % 384;
        g_wt1[idx] = __float2half_rn(W1[(size_t)k * 128 + n]);
    }
}
// wt2-5 (needed after agg1; runs on side stream, hidden)
__global__ void k_wtrans_rest(const float* __restrict__ W2, const float* __restrict__ W3,
                              const float* __restrict__ W4, const float* __restrict__ W5) {
    int idx = blockIdx.x * 256 + threadIdx.x;
    if (idx < 16384) {
        int n = idx / 128, k = idx % 128;
        g_wt2[idx] = __float2half_rn(W2[(size_t)k * 128 + n]);
    } else if (idx < 32768) {
        int j = idx - 16384; int n = j / 128, k = j % 128;
        g_wt3[j] = __float2half_rn(W3[(size_t)k * 128 + n]);
    } else if (idx < 49152) {
        int j = idx - 32768; int n = j / 128, k = j % 128;
        g_wt4[j] = __float2half_rn(W4[(size_t)k * 128 + n]);
    } else if (idx < 49152 + 8192) {
        int j = idx - 49152; int n = j / 128, k = j % 128;
        g_wt5[j] = (n < 50) ? __float2half_rn(W5[(size_t)k * 50 + n]) : __float2half_rn(0.f);
    }
}

// ---------------- GEMM1: fp32 A (fused cvt), 2-stage smem, single reg buffer --
template<int KT, int BN, int SC>
__global__ __launch_bounds__(256, 2) void k_gemm_cvt(const float* __restrict__ A32,
                                                     const __half* __restrict__ WT,
                                                     __half* __restrict__ C, int M) {
    constexpr int BM = 128, BKH = 32;
    constexpr int WTN = BN / 4;
    constexpr int NTL = WTN / 8;
    constexpr int LDR = BKH + 8;            // 40 halves = 80B rows
    constexpr int NK  = KT / BKH;
    constexpr int AST = BM * LDR;
    constexpr int WST = BN * LDR;
    constexpr int WCH = BN * 4 / 256;

    extern __shared__ __half smem[];
    __half* Abase = smem;                    // 2 stages
    __half* Wbase = smem + 2 * AST;

    const int tid = threadIdx.x;
    const int wid = tid >> 5;
    const int lane = tid & 31;
    const int g = lane >> 2;
    const int t = lane & 3;
    const int warp_m = wid >> 2;
    const int warp_n = wid & 3;
    const int row0 = blockIdx.x * BM;

    const uint32_t sA = (uint32_t)__cvta_generic_to_shared(Abase);
    const uint32_t sW = (uint32_t)__cvta_generic_to_shared(Wbase);

    float acc[4][NTL][4];
    #pragma unroll
    for (int i = 0; i < 4; i++)
        #pragma unroll
        for (int j = 0; j < NTL; j++)
            #pragma unroll
            for (int r = 0; r < 4; r++) acc[i][j][r] = 0.f;

    float4 pa[4];

    auto cpW = [&](int i, int st) {
        const int kb = i * BKH;
        #pragma unroll
        for (int j = 0; j < WCH; j++) {
            int idx = tid + j * 256;
            int n = idx >> 2, ch = idx & 3;
            cp_async16(sW + (uint32_t)((st * WST + n * LDR + ch * 8) * 2),
                       WT + (size_t)n * KT + kb + ch * 8, 16);
        }
    };
    auto ldA = [&](int i) {
        const int kb = i * BKH;
        #pragma unroll
        for (int j = 0; j < 4; j++) {
            int idx = tid + j * 256;
            int r = idx >> 3, c4 = idx & 7;
            int grow = row0 + r;
            pa[j] = (grow < M)
                ? __ldg((const float4*)(A32 + (size_t)grow * KT + kb + c4 * 4))
                : make_float4(0.f, 0.f, 0.f, 0.f);
        }
    };
    auto stsA = [&](int st) {
        #pragma unroll
        for (int j = 0; j < 4; j++) {
            int idx = tid + j * 256;
            int r = idx >> 3, c4 = idx & 7;
            __half2 h0 = __floats2half2_rn(pa[j].x, pa[j].y);
            __half2 h1 = __floats2half2_rn(pa[j].z, pa[j].w);
            uint2 u;
            u.x = *(uint32_t*)&h0;
            u.y = *(uint32_t*)&h1;
            *(uint2*)(Abase + st * AST + r * LDR + c4 * 4) = u;
        }
    };
    auto compute = [&](int st) {
        #pragma unroll
        for (int ks = 0; ks < 2; ks++) {
            const int k16 = ks * 16;
            uint32_t bf[NTL][2];
            #pragma unroll
            for (int np = 0; np < NTL / 2; np++) {
                int n0 = warp_n * WTN + np * 16;
                uint32_t ad = sW + (uint32_t)(((st * WST) +
                              (n0 + (lane & 7) + ((lane >> 4) & 1) * 8) * LDR +
                              k16 + ((lane >> 3) & 1) * 8) * 2);
                ldsm_x4(bf[2 * np][0], bf[2 * np][1], bf[2 * np + 1][0], bf[2 * np + 1][1], ad);
            }
            #pragma unroll
            for (int mt = 0; mt < 4; mt++) {
                int mb = warp_m * 64 + mt * 16;
                uint32_t ad = sA + (uint32_t)(((st * AST) +
                              (mb + (lane & 15)) * LDR + k16 + (lane >> 4) * 8) * 2);
                uint32_t a0, a1, a2, a3;
                ldsm_x4(a0, a1, a2, a3, ad);
                #pragma unroll
                for (int nt = 0; nt < NTL; nt++) {
                    asm volatile(
                        "mma.sync.aligned.m16n8k16.row.col.f32.f16.f16.f32 "
                        "{%0,%1,%2,%3}, {%4,%5,%6,%7}, {%8,%9}, {%0,%1,%2,%3};"
                        : "+f"(acc[mt][nt][0]), "+f"(acc[mt][nt][1]),
                          "+f"(acc[mt][nt][2]), "+f"(acc[mt][nt][3])
                        : "r"(a0), "r"(a1), "r"(a2), "r"(a3),
                          "r"(bf[nt][0]), "r"(bf[nt][1]));
                }
            }
        }
    };

    ldA(0);
    cpW(0, 0); cp_commit();
    stsA(0);
    ldA(1);
    cpW(1, 1); cp_commit();
    cp_wait<1>();
    __syncthreads();

    for (int i = 0; i < NK; i++) {
        const int st = i & 1;
        compute(st);
        __syncthreads();                       // stage st fully consumed
        if (i + 1 < NK) stsA((i + 1) & 1);     // A(i+1) regs -> other stage
        if (i + 2 < NK) { ldA(i + 2); cpW(i + 2, st); }
        cp_commit();
        cp_wait<1>();
        __syncthreads();
    }

    // ---- epilogue: stage C in smem, coalesced STG.128 ----
    __syncthreads();
    constexpr int CLDR = BN + 8;
    __half* Cs = smem;
    #pragma unroll
    for (int mt = 0; mt < 4; mt++) {
        int rl = warp_m * 64 + mt * 16 + g;
        #pragma unroll
        for (int nt = 0; nt < NTL; nt++) {
            int col = warp_n * WTN + nt * 8 + t * 2;
            *(__half2*)(Cs + rl * CLDR + col) =
                __floats2half2_rn(acc[mt][nt][0], acc[mt][nt][1]);
            *(__half2*)(Cs + (rl + 8) * CLDR + col) =
                __floats2half2_rn(acc[mt][nt][2], acc[mt][nt][3]);
        }
    }
    __syncthreads();
    constexpr int CH8 = BN / 8;
    #pragma unroll
    for (int j = 0; j < (BM * CH8) / 256; j++) {
        int idx = tid + j * 256;
        int r = idx / CH8, c8 = idx % CH8;
        int grow = row0 + r;
        if (grow < M)
            *(uint4*)(C + (size_t)grow * SC + c8 * 8) = *(uint4*)(Cs + r * CLDR + c8 * 8);
    }
}

// ---------------- flat fp16 GEMM (K=128): one smem fill, zero in-loop syncs ---
template<int BN, int SC>
__global__ __launch_bounds__(256, 2) void k_gemm_flat(const __half* __restrict__ A,
                                                      const __half* __restrict__ WT,
                                                      __half* __restrict__ C, int M) {
    constexpr int KT = 128, BM = 128;
    constexpr int WTN = BN / 4;
    constexpr int NTL = WTN / 8;
    constexpr int LDR = KT + 8;             // 136 halves = 272B rows, conflict-free
    constexpr int WCH = BN * 16 / 256;      // W 16B-chunks per thread (8 or 4)

    extern __shared__ __half smem[];
    __half* As = smem;                      // [BM][LDR]
    __half* Ws = smem + BM * LDR;           // [BN][LDR]

    const int tid = threadIdx.x;
    const int wid = tid >> 5;
    const int lane = tid & 31;
    const int g = lane >> 2;
    const int t = lane & 3;
    const int warp_m = wid >> 2;
    const int warp_n = wid & 3;
    const int row0 = blockIdx.x * BM;

    const uint32_t sA = (uint32_t)__cvta_generic_to_shared(As);
    const uint32_t sW = (uint32_t)__cvta_generic_to_shared(Ws);

    // ---- single cp.async burst: whole A tile + whole W ----
    #pragma unroll
    for (int j = 0; j < 8; j++) {                   // A: 128 rows x 16 chunks
        int idx = tid + j * 256;
        int r = idx >> 4, ch = idx & 15;
        int grow = row0 + r;
        cp_async16(sA + (uint32_t)((r * LDR + ch * 8) * 2),
                   A + (size_t)grow * KT + ch * 8, grow < M ? 16 : 0);
    }
    #pragma unroll
    for (int j = 0; j < WCH; j++) {                 // W: BN rows x 16 chunks
        int idx = tid + j * 256;
        int r = idx >> 4, ch = idx & 15;
        cp_async16(sW + (uint32_t)((r * LDR + ch * 8) * 2),
                   WT + (size_t)r * KT + ch * 8, 16);
    }
    cp_commit();

    float acc[4][NTL][4];
    #pragma unroll
    for (int i = 0; i < 4; i++)
        #pragma unroll
        for (int j = 0; j < NTL; j++)
            #pragma unroll
            for (int r = 0; r < 4; r++) acc[i][j][r] = 0.f;

    cp_wait<0>();
    __syncthreads();

    // ---- 8 uninterrupted k16 steps ----
    #pragma unroll
    for (int ks = 0; ks < 8; ks++) {
        const int k16 = ks * 16;
        uint32_t bf[NTL][2];
        #pragma unroll
        for (int np = 0; np < NTL / 2; np++) {
            int n0 = warp_n * WTN + np * 16;
            uint32_t ad = sW + (uint32_t)(((n0 + (lane & 7) + ((lane >> 4) & 1) * 8) * LDR +
                          k16 + ((lane >> 3) & 1) * 8) * 2);
            ldsm_x4(bf[2 * np][0], bf[2 * np][1], bf[2 * np + 1][0], bf[2 * np + 1][1], ad);
        }
        #pragma unroll
        for (int mt = 0; mt < 4; mt++) {
            int mb = warp_m * 64 + mt * 16;
            uint32_t ad = sA + (uint32_t)(((mb + (lane & 15)) * LDR + k16 + (lane >> 4) * 8) * 2);
            uint32_t a0, a1, a2, a3;
            ldsm_x4(a0, a1, a2, a3, ad);
            #pragma unroll
            for (int nt = 0; nt < NTL; nt++) {
                asm volatile(
                    "mma.sync.aligned.m16n8k16.row.col.f32.f16.f16.f32 "
                    "{%0,%1,%2,%3}, {%4,%5,%6,%7}, {%8,%9}, {%0,%1,%2,%3};"
                    : "+f"(acc[mt][nt][0]), "+f"(acc[mt][nt][1]),
                      "+f"(acc[mt][nt][2]), "+f"(acc[mt][nt][3])
                    : "r"(a0), "r"(a1), "r"(a2), "r"(a3),
                      "r"(bf[nt][0]), "r"(bf[nt][1]));
            }
        }
    }

    // ---- epilogue: stage C in smem, coalesced STG.128 ----
    __syncthreads();
    constexpr int CLDR = BN + 8;
    __half* Cs = smem;
    #pragma unroll
    for (int mt = 0; mt < 4; mt++) {
        int rl = warp_m * 64 + mt * 16 + g;
        #pragma unroll
        for (int nt = 0; nt < NTL; nt++) {
            int col = warp_n * WTN + nt * 8 + t * 2;
            *(__half2*)(Cs + rl * CLDR + col) =
                __floats2half2_rn(acc[mt][nt][0], acc[mt][nt][1]);
            *(__half2*)(Cs + (rl + 8) * CLDR + col) =
                __floats2half2_rn(acc[mt][nt][2], acc[mt][nt][3]);
        }
    }
    __syncthreads();
    constexpr int CH8 = BN / 8;
    #pragma unroll
    for (int j = 0; j < (BM * CH8) / 256; j++) {
        int idx = tid + j * 256;
        int r = idx / CH8, c8 = idx % CH8;
        int grow = row0 + r;
        if (grow < M)
            *(uint4*)(C + (size_t)grow * SC + c8 * 8) = *(uint4*)(Cs + r * CLDR + c8 * 8);
    }
}

// ---------------- aggregation (C=128): warp per node, packed edges -----------
__global__ __launch_bounds__(256) void k_agg128(const __half* __restrict__ hin,
                                                const float* __restrict__ b,
                                                __half* __restrict__ out, int n) {
    int warp = (blockIdx.x * blockDim.x + threadIdx.x) >> 5;
    int lane = threadIdx.x & 31;
    if (warp >= n) return;
    const uint2* __restrict__ h2 = (const uint2*)hin;   // 4 halves per uint2; 32/row
    int e = g_rowptr[warp];
    const int e1 = g_rowptr[warp + 1];

    float4 acc = make_float4(0.f, 0.f, 0.f, 0.f);

    for (; e + 8 <= e1; e += 8) {
        uint2 p[8]; uint2 v[8];
        #pragma unroll
        for (int j = 0; j < 8; j++) p[j] = __ldg(g_epk + e + j);
        #pragma unroll
        for (int j = 0; j < 8; j++) v[j] = __ldg(h2 + p[j].x * 32 + lane);
        #pragma unroll
        for (int j = 0; j < 8; j++) {
            float w = __uint_as_float(p[j].y);
            float2 f0 = __half22float2(*(__half2*)&v[j].x);
            float2 f1 = __half22float2(*(__half2*)&v[j].y);
            acc.x += w * f0.x; acc.y += w * f0.y;
            acc.z += w * f1.x; acc.w += w * f1.y;
        }
    }
    for (; e < e1; e++) {
        uint2 p = __ldg(g_epk + e);
        float w = __uint_as_float(p.y);
        uint2 v0 = __ldg(h2 + p.x * 32 + lane);
        float2 f0 = __half22float2(*(__half2*)&v0.x);
        float2 f1 = __half22float2(*(__half2*)&v0.y);
        acc.x += w * f0.x; acc.y += w * f0.y;
        acc.z += w * f1.x; acc.w += w * f1.y;
    }

    float di = g_dinv[warp];
    float sl = di * di;
    uint2 vr = __ldg(h2 + warp * 32 + lane);
    float2 vi0 = __half22float2(*(__half2*)&vr.x);
    float2 vi1 = __half22float2(*(__half2*)&vr.y);
    float4 vb = __ldg((const float4*)b + lane);
    __half2 o0 = __floats2half2_rn(fmaxf(acc.x + sl * vi0.x + vb.x, 0.f),
                                   fmaxf(acc.y + sl * vi0.y + vb.y, 0.f));
    __half2 o1 = __floats2half2_rn(fmaxf(acc.z + sl * vi1.x + vb.z, 0.f),
                                   fmaxf(acc.w + sl * vi1.y + vb.w, 0.f));
    uint2 o;
    o.x = *(uint32_t*)&o0;
    o.y = *(uint32_t*)&o1;
    ((uint2*)out)[warp * 32 + lane] = o;
}

// ---------------- final aggregation (C=50, half input, no relu) --------------
__global__ __launch_bounds__(256) void k_agg_fin(const __half* __restrict__ h,
                                                 const float* __restrict__ b,
                                                 float* __restrict__ out, int n) {
    int warp = (blockIdx.x * blockDim.x + threadIdx.x) >> 5;
    int lane = threadIdx.x & 31;
    if (warp >= n) return;
    const int i = warp;
    int e = g_rowptr[i];
    const int e1 = g_rowptr[i + 1];
    const int f0 = lane;            // < 32
    const int f1 = lane + 32;       // < 50 for lanes 0..17

    float a0 = 0.f, a1 = 0.f;
    for (; e + 4 <= e1; e += 4) {
        uint2 p0 = __ldg(g_epk + e),     p1 = __ldg(g_epk + e + 1);
        uint2 p2 = __ldg(g_epk + e + 2), p3 = __ldg(g_epk + e + 3);
        float n0 = __uint_as_float(p0.y), n1 = __uint_as_float(p1.y);
        float n2 = __uint_as_float(p2.y), n3 = __uint_as_float(p3.y);
        const __half* q0 = h + (size_t)p0.x * 64;
        const __half* q1 = h + (size_t)p1.x * 64;
        const __half* q2 = h + (size_t)p2.x * 64;
        const __half* q3 = h + (size_t)p3.x * 64;
        a0 += n0 * __half2float(__ldg(q0 + f0));
        a0 += n1 * __half2float(__ldg(q1 + f0));
        a0 += n2 * __half2float(__ldg(q2 + f0));
        a0 += n3 * __half2float(__ldg(q3 + f0));
        if (f1 < 50) {
            a1 += n0 * __half2float(__ldg(q0 + f1));
            a1 += n1 * __half2float(__ldg(q1 + f1));
            a1 += n2 * __half2float(__ldg(q2 + f1));
            a1 += n3 * __half2float(__ldg(q3 + f1));
        }
    }
    for (; e < e1; e++) {
        uint2 p = __ldg(g_epk + e);
        float n0 = __uint_as_float(p.y);
        const __half* q0 = h + (size_t)p.x * 64;
        a0 += n0 * __half2float(__ldg(q0 + f0));
        if (f1 < 50) a1 += n0 * __half2float(__ldg(q0 + f1));
    }

    float di = g_dinv[i];
    float sl = di * di;
    const __half* hi = h + (size_t)i * 64;
    out[(size_t)i * 50 + f0] = a0 + sl * __half2float(__ldg(hi + f0)) + __ldg(b + f0);
    if (f1 < 50)
        out[(size_t)i * 50 + f1] = a1 + sl * __half2float(__ldg(hi + f1)) + __ldg(b + f1);
}

// ---------------- launch ----------------
extern "C" void kernel_launch(void* const* d_in, const int* in_sizes, int n_in,
                              void* d_out, int out_size) {
    const float* x  = (const float*)d_in[0];
    const void*  ei = d_in[1];
    const float* W1 = (const float*)d_in[2];  const float* b1 = (const float*)d_in[3];
    const float* W2 = (const float*)d_in[4];  const float* b2 = (const float*)d_in[5];
    const float* W3 = (const float*)d_in[6];  const float* b3 = (const float*)d_in[7];
    const float* W4 = (const float*)d_in[8];  const float* b4 = (const float*)d_in[9];
    const float* W5 = (const float*)d_in[10]; const float* b5 = (const float*)d_in[11];

    const int N = in_sizes[0] / 384;
    const int E = in_sizes[1] / 2;

    __half *h, *y, *wt1, *wt2, *wt3, *wt4, *wt5;
    cudaGetSymbolAddress((void**)&h, g_h);
    cudaGetSymbolAddress((void**)&y, g_y);
    cudaGetSymbolAddress((void**)&wt1, g_wt1);
    cudaGetSymbolAddress((void**)&wt2, g_wt2);
    cudaGetSymbolAddress((void**)&wt3, g_wt3);
    cudaGetSymbolAddress((void**)&wt4, g_wt4);
    cudaGetSymbolAddress((void**)&wt5, g_wt5);

    const int T = 256;
    const int gN = (N + T - 1) / T;
    const int gE2 = (E / 2 + T) / T;        // 2 edges per thread
    const int nb = (N + 1023) / 1024;
    const int gm = (N + 127) / 128;
    const int ga = (N + 7) / 8;

    const int smemCVT  = 2 * (128 + 128) * 40 * 2;  // 40960
    const int smemF128 = (128 + 128) * 136 * 2;     // 69632
    const int smemF64  = (128 + 64) * 136 * 2;      // 52224
    cudaFuncSetAttribute(k_gemm_cvt<384, 128, 128>,
                         cudaFuncAttributeMaxDynamicSharedMemorySize, smemCVT);
    cudaFuncSetAttribute(k_gemm_flat<128, 128>,
                         cudaFuncAttributeMaxDynamicSharedMemorySize, smemF128);
    cudaFuncSetAttribute(k_gemm_flat<64, 64>,
                         cudaFuncAttributeMaxDynamicSharedMemorySize, smemF64);

    // lazily-created side stream + fork/join events (host handles only)
    static cudaStream_t s2 = nullptr;
    static cudaEvent_t evFork = nullptr, evJoin = nullptr;
    if (s2 == nullptr) {
        cudaStreamCreateWithFlags(&s2, cudaStreamNonBlocking);
        cudaEventCreateWithFlags(&evFork, cudaEventDisableTiming);
        cudaEventCreateWithFlags(&evJoin, cudaEventDisableTiming);
    }

    // ---- fork: CSR build (+ wt2-5 transpose) on s2, GEMM1 path on main ----
    cudaEventRecord(evFork, 0);
    cudaStreamWaitEvent(s2, evFork, 0);

    k_init<<<gN, T, 0, s2>>>(ei, E, (long long)N, N);
    k_hist<<<gE2, T, 0, s2>>>(ei, E);
    k_scan1<<<nb, 1024, 0, s2>>>(N);
    k_scan2<<<1, 256, 0, s2>>>(nb, N);
    k_scan3<<<gN, T, 0, s2>>>(N);
    k_scatter<<<gE2, T, 0, s2>>>(ei, E);
    k_wtrans_rest<<<(57344 + 255) / 256, T, 0, s2>>>(W2, W3, W4, W5);
    cudaEventRecord(evJoin, s2);

    k_wtrans1<<<(49152 + 255) / 256, T>>>(W1);
    k_gemm_cvt<384, 128, 128><<<gm, T, smemCVT>>>(x, wt1, h, N);   // GEMM1 (+cvt)

    // ---- join: aggregation needs both GEMM1 output and the CSR ----
    cudaStreamWaitEvent(0, evJoin, 0);

    // layer 1 aggregation (half gathers -> fp16 y)
    k_agg128<<<ga, T>>>(h, b1, y, N);
    // layers 2-4 (flat GEMMs)
    k_gemm_flat<128, 128><<<gm, T, smemF128>>>(y, wt2, h, N);
    k_agg128<<<ga, T>>>(h, b2, y, N);
    k_gemm_flat<128, 128><<<gm, T, smemF128>>>(y, wt3, h, N);
    k_agg128<<<ga, T>>>(h, b3, y, N);
    k_gemm_flat<128, 128><<<gm, T, smemF128>>>(y, wt4, h, N);
    k_agg128<<<ga, T>>>(h, b4, y, N);
    // layer 5: 128 -> 50 (64 padded cols), then final aggregation
    k_gemm_flat<64, 64><<<gm, T, smemF64>>>(y, wt5, h, N);
    k_agg_fin<<<ga, T>>>(h, b5, (float*)d_out, N);
}